// round 7
// baseline (speedup 1.0000x reference)
#include <cuda_runtime.h>
#include <math.h>

// ---------------- scratch (device globals) ----------------
__device__ float g_bufA[33554432];  // 16x128x128x128
__device__ float g_bufB[16777216];  // 16x256x64x64
__device__ float g_bufC[8388608];   // 16x512x32x32
__device__ float g_bufZ[524288];    // 16x32x32x32
__device__ float g_bufQ[524288];
__device__ float g_mean[512];
__device__ float g_rstd[512];

// packed f32x2 FMA: acc.x += a.x*b.x ; acc.y += a.y*b.y
__device__ __forceinline__ void ffma2(float2& acc, float2 a, float2 b) {
    unsigned long long ua = *reinterpret_cast<unsigned long long*>(&a);
    unsigned long long ub = *reinterpret_cast<unsigned long long*>(&b);
    unsigned long long uc = *reinterpret_cast<unsigned long long*>(&acc);
    asm("fma.rn.f32x2 %0, %1, %2, %0;" : "+l"(uc) : "l"(ua), "l"(ub));
    acc = *reinterpret_cast<float2*>(&uc);
}

// =============== stride-2 4x4 conv pad 1: 128 co x (8 rows x 16 cols) px per block ===============
// thread: colx = tid&15 (px column), cog = tid>>4 (8 co). acc = 8 rows x 4 co-pairs (f32x2).
__global__ __launch_bounds__(256) void conv_s2_big(
    const float* __restrict__ in, const float* __restrict__ w,
    const float* __restrict__ bias, float* __restrict__ out,
    int Cin, int Cout, int Hin, int Win)
{
    const int Hout = Hin >> 1, Wout = Win >> 1;
    const int tilesX = Wout >> 4;
    const int oh0 = (blockIdx.x / tilesX) << 3;
    const int ow0 = (blockIdx.x % tilesX) << 4;
    const int cob = blockIdx.y << 7;
    const int n = blockIdx.z;

    __shared__ float P[4][18][36];                    // 18 rows x 34 cols used
    __shared__ __align__(16) float Wt[4][16][132];    // [c][khw][co], row 528B (16B mult)

    const int tid = threadIdx.x;
    const int colx = tid & 15;
    const int cog  = tid >> 4;

    float2 acc[8][4];
#pragma unroll
    for (int r = 0; r < 8; ++r)
#pragma unroll
        for (int k = 0; k < 4; ++k) acc[r][k] = make_float2(0.f, 0.f);

    const float* inb = in + (size_t)n * Cin * Hin * Win;

    for (int c0 = 0; c0 < Cin; c0 += 4) {
        // weights: [c][khw][co]
        for (int idx = tid; idx < 8192; idx += 256) {
            int khw = idx & 15, r = idx >> 4;
            int co = r & 127, c = r >> 7;
            float v = 0.f;
            if (c0 + c < Cin)
                v = w[((size_t)(cob + co) * Cin + c0 + c) * 16 + khw];
            Wt[c][khw][co] = v;
        }
        // input patch: 4 ch x 18 x 34
        for (int idx = tid; idx < 2448; idx += 256) {
            int c = idx / 612, r = idx - c * 612;
            int pr = r / 34, pc = r - pr * 34;
            int ih = 2 * oh0 - 1 + pr, iw = 2 * ow0 - 1 + pc;
            float v = 0.f;
            if (c0 + c < Cin && (unsigned)ih < (unsigned)Hin && (unsigned)iw < (unsigned)Win)
                v = inb[((size_t)(c0 + c) * Hin + ih) * Win + iw];
            P[c][pr][pc] = v;
        }
        __syncthreads();

#pragma unroll 1
        for (int c = 0; c < 4; ++c) {
#pragma unroll
            for (int kh = 0; kh < 4; ++kh) {
#pragma unroll
                for (int kw = 0; kw < 4; ++kw) {
                    float2 a2[8];
#pragma unroll
                    for (int r = 0; r < 8; ++r) {
                        float a = P[c][2 * r + kh][2 * colx + kw];
                        a2[r] = make_float2(a, a);
                    }
                    const float4* wr = reinterpret_cast<const float4*>(&Wt[c][(kh << 2) + kw][cog << 3]);
                    float4 wA = wr[0], wB = wr[1];
                    float2 wp0 = make_float2(wA.x, wA.y);
                    float2 wp1 = make_float2(wA.z, wA.w);
                    float2 wp2 = make_float2(wB.x, wB.y);
                    float2 wp3 = make_float2(wB.z, wB.w);
#pragma unroll
                    for (int r = 0; r < 8; ++r) {
                        ffma2(acc[r][0], a2[r], wp0);
                        ffma2(acc[r][1], a2[r], wp1);
                        ffma2(acc[r][2], a2[r], wp2);
                        ffma2(acc[r][3], a2[r], wp3);
                    }
                }
            }
        }
        __syncthreads();
    }

#pragma unroll
    for (int kp = 0; kp < 4; ++kp) {
        int co = cob + (cog << 3) + (kp << 1);
        float b0 = bias[co], b1 = bias[co + 1];
        float* o0 = out + (((size_t)n * Cout + co) * Hout + oh0) * Wout + ow0 + colx;
        float* o1 = o0 + (size_t)Hout * Wout;
#pragma unroll
        for (int r = 0; r < 8; ++r) {
            o0[(size_t)r * Wout] = acc[r][kp].x + b0;
            o1[(size_t)r * Wout] = acc[r][kp].y + b1;
        }
    }
}

// =============== transposed conv k4 s2 p1: 128 co x (8 rows x 16 cols) out px per block ===============
// acc pairs over (even,odd) output rows; weights pre-paired (kh_even, kh_odd) per tap.
__global__ __launch_bounds__(256) void convt_big(
    const float* __restrict__ in, const float* __restrict__ w,
    const float* __restrict__ bias, float* __restrict__ out,
    int Cin, int Cout, int Hin, int Win)
{
    const int Hout = Hin << 1, Wout = Win << 1;
    const int tilesX = Wout >> 4;
    const int oh0 = (blockIdx.x / tilesX) << 3;
    const int ow0 = (blockIdx.x % tilesX) << 4;
    const int cob = blockIdx.y << 7;
    const int n = blockIdx.z;

    __shared__ float P[4][6][12];                          // 6 rows x 10 cols used
    __shared__ __align__(16) float2 Wp[4][2][2][2][130];   // [c][dh][dw][pw][co] 128 co + pad

    const int tid = threadIdx.x;
    const int colx = tid & 15;
    const int cog  = tid >> 4;
    const int pw = colx & 1;
    const int iwl0 = (colx + pw) >> 1;
    const int r0 = (oh0 >> 1) - 1;
    const int col0 = (ow0 >> 1) - 1;

    float2 acc[4][8];  // [row-pair t][co k]
#pragma unroll
    for (int t = 0; t < 4; ++t)
#pragma unroll
        for (int k = 0; k < 8; ++k) acc[t][k] = make_float2(0.f, 0.f);

    const float* inb = in + (size_t)n * Cin * Hin * Win;

    for (int c0 = 0; c0 < Cin; c0 += 4) {
        // pre-paired weights: (kh=2dh, kh=2dh+1) at kw=2dw+pw
        for (int idx = tid; idx < 4096; idx += 256) {
            int p = idx & 7;
            int co = (idx >> 3) & 127;
            int c = idx >> 10;
            int dh = p >> 2, dw = (p >> 1) & 1, pww = p & 1;
            size_t base = ((size_t)(cob + co) * Cin + c0 + c) * 16 + (dh << 3) + (dw << 1) + pww;
            Wp[c][dh][dw][pww][co] = make_float2(w[base], w[base + 4]);
        }
        // input patch 4 ch x 6 x 10
        for (int idx = tid; idx < 240; idx += 256) {
            int c = idx / 60, r = idx - c * 60;
            int pr = r / 10, pc = r - pr * 10;
            int ih = r0 + pr, iw = col0 + pc;
            float v = 0.f;
            if ((unsigned)ih < (unsigned)Hin && (unsigned)iw < (unsigned)Win)
                v = inb[((size_t)(c0 + c) * Hin + ih) * Win + iw];
            P[c][pr][pc] = v;
        }
        __syncthreads();

#pragma unroll 1
        for (int c = 0; c < 4; ++c) {
#pragma unroll
            for (int dh = 0; dh < 2; ++dh) {
#pragma unroll
                for (int dw = 0; dw < 2; ++dw) {
                    float a[5];
#pragma unroll
                    for (int t = 0; t < 5; ++t)
                        a[t] = P[c][t + dh][iwl0 + dw];
                    float2 ap[4];
#pragma unroll
                    for (int t = 0; t < 4; ++t)
                        ap[t] = make_float2(a[t], a[t + 1]);
                    const float4* wr = reinterpret_cast<const float4*>(&Wp[c][dh][dw][pw][cog << 3]);
                    float2 wp2[8];
#pragma unroll
                    for (int q = 0; q < 4; ++q) {
                        float4 v = wr[q];
                        wp2[2 * q]     = make_float2(v.x, v.y);
                        wp2[2 * q + 1] = make_float2(v.z, v.w);
                    }
#pragma unroll
                    for (int t = 0; t < 4; ++t)
#pragma unroll
                        for (int k = 0; k < 8; ++k)
                            ffma2(acc[t][k], ap[t], wp2[k]);
                }
            }
        }
        __syncthreads();
    }

#pragma unroll
    for (int k = 0; k < 8; ++k) {
        int co = cob + (cog << 3) + k;
        float b = bias[co];
        float* ob = out + (((size_t)n * Cout + co) * Hout + oh0) * Wout + ow0 + colx;
#pragma unroll
        for (int t = 0; t < 4; ++t) {
            ob[(size_t)(2 * t) * Wout]     = acc[t][k].x + b;
            ob[(size_t)(2 * t + 1) * Wout] = acc[t][k].y + b;
        }
    }
}

// =============== final transposed conv 128->3 + tanh ===============
__global__ __launch_bounds__(256) void convt_final_kernel(
    const float* __restrict__ in, const float* __restrict__ w,
    const float* __restrict__ bias, float* __restrict__ out)
{
    const int n = blockIdx.y;
    const int oh0 = (blockIdx.x >> 4) << 4;
    const int ow0 = (blockIdx.x & 15) << 4;
    __shared__ float P[8][10][11];
    __shared__ float Wsm[8][3][17];
    const int tid = threadIdx.x;
    const int py = tid >> 4, px = tid & 15;
    const int ph = py & 1, pw = px & 1;
    const int ihl0 = (py + ph) >> 1, iwl0 = (px + pw) >> 1;
    const int r0 = (oh0 >> 1) - 1, col0 = (ow0 >> 1) - 1;
    float acc0 = 0.f, acc1 = 0.f, acc2 = 0.f;
    const float* inb = in + ((size_t)n << 21);

    for (int c0 = 0; c0 < 128; c0 += 8) {
        for (int idx = tid; idx < 800; idx += 256) {
            int c = idx / 100, r = idx - c * 100;
            int rr = r / 10, cc = r - rr * 10;
            int ih = r0 + rr, iw = col0 + cc;
            float v = 0.f;
            if ((unsigned)ih < 128u && (unsigned)iw < 128u)
                v = inb[((size_t)(c0 + c) << 14) + (ih << 7) + iw];
            P[c][rr][cc] = v;
        }
        for (int idx = tid; idx < 384; idx += 256) {
            int c = idx / 48, r = idx - c * 48;
            int co = r >> 4, khw = r & 15;
            Wsm[c][co][khw] = w[((size_t)co * 128 + c0 + c) * 16 + khw];
        }
        __syncthreads();
#pragma unroll
        for (int c = 0; c < 8; ++c) {
#pragma unroll
            for (int dh = 0; dh < 2; ++dh) {
#pragma unroll
                for (int dw = 0; dw < 2; ++dw) {
                    float a = P[c][ihl0 + dh][iwl0 + dw];
                    int khw = ((ph + (dh << 1)) << 2) + pw + (dw << 1);
                    acc0 += a * Wsm[c][0][khw];
                    acc1 += a * Wsm[c][1][khw];
                    acc2 += a * Wsm[c][2][khw];
                }
            }
        }
        __syncthreads();
    }
    const int oh = oh0 + py, ow = ow0 + px;
    size_t base = ((size_t)n * 3) * 65536 + ((size_t)oh << 8) + ow;
    out[base]          = tanhf(acc0 + bias[0]);
    out[base + 65536]  = tanhf(acc1 + bias[1]);
    out[base + 131072] = tanhf(acc2 + bias[2]);
}

// =============== group-norm stats ===============
__global__ __launch_bounds__(256) void gn_stats_kernel(const float* __restrict__ x, int span)
{
    const float* p = x + (size_t)blockIdx.x * span;
    float s = 0.f, ss = 0.f;
    for (int i = threadIdx.x; i < span; i += 256) {
        float v = p[i];
        s += v; ss += v * v;
    }
#pragma unroll
    for (int o = 16; o; o >>= 1) {
        s  += __shfl_down_sync(0xffffffffu, s, o);
        ss += __shfl_down_sync(0xffffffffu, ss, o);
    }
    __shared__ float as[8], bs[8];
    int wi = threadIdx.x >> 5, l = threadIdx.x & 31;
    if (l == 0) { as[wi] = s; bs[wi] = ss; }
    __syncthreads();
    if (threadIdx.x == 0) {
        s = 0.f; ss = 0.f;
#pragma unroll
        for (int i = 0; i < 8; ++i) { s += as[i]; ss += bs[i]; }
        float m = s / (float)span;
        float var = ss / (float)span - m * m;
        g_mean[blockIdx.x] = m;
        g_rstd[blockIdx.x] = rsqrtf(var + 1e-5f);
    }
}

// =============== fused GN apply + SiLU ===============
__global__ __launch_bounds__(256) void gn_apply_silu_kernel(
    float* __restrict__ x, const float* __restrict__ gamma, const float* __restrict__ beta,
    int C, int HW, int cpg)
{
    size_t i = (size_t)blockIdx.x * 256 + threadIdx.x;
    size_t e = i * 4;
    size_t ch = e / (size_t)HW;
    int c = (int)(ch % C);
    int n = (int)(ch / C);
    int gi = n * 32 + c / cpg;
    float m = g_mean[gi], r = g_rstd[gi];
    float ga = gamma[c], be = beta[c];
    float4 v = *reinterpret_cast<float4*>(x + e);
    float y;
    y = (v.x - m) * r * ga + be; v.x = y / (1.f + expf(-y));
    y = (v.y - m) * r * ga + be; v.y = y / (1.f + expf(-y));
    y = (v.z - m) * r * ga + be; v.z = y / (1.f + expf(-y));
    y = (v.w - m) * r * ga + be; v.w = y / (1.f + expf(-y));
    *reinterpret_cast<float4*>(x + e) = v;
}

// =============== 1x1 conv 512->32 ===============
__global__ __launch_bounds__(256) void conv1x1_enc3_kernel(
    const float* __restrict__ in, const float* __restrict__ w,
    const float* __restrict__ bias, float* __restrict__ out)
{
    const int t = blockIdx.x * 256 + threadIdx.x;
    const int n = t >> 10, pix = t & 1023;
    __shared__ float wsm[128][33];
    float acc[32];
#pragma unroll
    for (int k = 0; k < 32; ++k) acc[k] = 0.f;
    for (int c0 = 0; c0 < 512; c0 += 128) {
        __syncthreads();
        for (int idx = threadIdx.x; idx < 4096; idx += 256) {
            int co = idx >> 7, cc = idx & 127;
            wsm[cc][co] = w[(size_t)co * 512 + c0 + cc];
        }
        __syncthreads();
        for (int cc = 0; cc < 128; ++cc) {
            float a = in[(((size_t)n * 512 + c0 + cc) << 10) + pix];
#pragma unroll
            for (int k = 0; k < 32; ++k) acc[k] += a * wsm[cc][k];
        }
    }
#pragma unroll
    for (int k = 0; k < 32; ++k)
        out[(((size_t)n * 32 + k) << 10) + pix] = acc[k] + bias[k];
}

// =============== vector quantization ===============
__global__ __launch_bounds__(256) void vq_kernel(
    const float* __restrict__ z, const float* __restrict__ cbk,
    float* __restrict__ q, float* __restrict__ outq, float* __restrict__ outidx)
{
    const int m = blockIdx.x * 256 + threadIdx.x;
    float v[32];
#pragma unroll
    for (int j = 0; j < 32; ++j) v[j] = z[(size_t)m * 32 + j];
    __shared__ float csm[128][33];
    __shared__ float c2sm[128];
    float best = 3.4e38f;
    int bi = 0;
    for (int k0 = 0; k0 < 1024; k0 += 128) {
        __syncthreads();
        for (int idx = threadIdx.x; idx < 4096; idx += 256)
            csm[idx >> 5][idx & 31] = cbk[(size_t)k0 * 32 + idx];
        __syncthreads();
        if (threadIdx.x < 128) {
            float s = 0.f;
#pragma unroll
            for (int j = 0; j < 32; ++j) { float c = csm[threadIdx.x][j]; s += c * c; }
            c2sm[threadIdx.x] = s;
        }
        __syncthreads();
        for (int k = 0; k < 128; ++k) {
            float dot = 0.f;
#pragma unroll
            for (int j = 0; j < 32; ++j) dot += v[j] * csm[k][j];
            float d = c2sm[k] - 2.f * dot;
            if (d < best) { best = d; bi = k0 + k; }
        }
    }
#pragma unroll
    for (int j = 0; j < 32; ++j) {
        float qv = cbk[(size_t)bi * 32 + j];
        q[(size_t)m * 32 + j] = qv;
        outq[(size_t)m * 32 + j] = qv;
    }
    outidx[m] = (float)bi;
}

// =============== 1x1 conv 32->512 ===============
__global__ __launch_bounds__(256) void conv1x1_dec0_kernel(
    const float* __restrict__ q, const float* __restrict__ w,
    const float* __restrict__ bias, float* __restrict__ out)
{
    const int n = blockIdx.x >> 4;
    const int pix0 = (blockIdx.x & 15) << 6;
    const int cob = blockIdx.y << 6;
    __shared__ float qsm[32][64];
    __shared__ float wsm[32][65];
    const int tid = threadIdx.x;
    const int p = tid & 63, cg = tid >> 6;
    for (int idx = tid; idx < 2048; idx += 256) {
        int ci = idx >> 6, pp = idx & 63;
        qsm[ci][pp] = q[(((size_t)n * 32 + ci) << 10) + pix0 + pp];
    }
    for (int idx = tid; idx < 2048; idx += 256) {
        int co = idx >> 5, ci = idx & 31;
        wsm[ci][co] = w[((size_t)(cob + co) << 5) + ci];
    }
    __syncthreads();
    float acc[16];
#pragma unroll
    for (int k = 0; k < 16; ++k) acc[k] = 0.f;
#pragma unroll
    for (int ci = 0; ci < 32; ++ci) {
        float a = qsm[ci][p];
#pragma unroll
        for (int k = 0; k < 16; ++k)
            acc[k] += a * wsm[ci][(cg << 4) + k];
    }
#pragma unroll
    for (int k = 0; k < 16; ++k) {
        int co = cob + (cg << 4) + k;
        out[(((size_t)n * 512 + co) << 10) + pix0 + p] = acc[k] + bias[co];
    }
}

// =================================================================================
extern "C" void kernel_launch(void* const* d_in, const int* in_sizes, int n_in,
                              void* d_out, int out_size)
{
    const float* x       = (const float*)d_in[0];
    const float* enc0_w  = (const float*)d_in[1];
    const float* enc0_b  = (const float*)d_in[2];
    const float* enc0_g  = (const float*)d_in[3];
    const float* enc0_bt = (const float*)d_in[4];
    const float* enc1_w  = (const float*)d_in[5];
    const float* enc1_b  = (const float*)d_in[6];
    const float* enc1_g  = (const float*)d_in[7];
    const float* enc1_bt = (const float*)d_in[8];
    const float* enc2_w  = (const float*)d_in[9];
    const float* enc2_b  = (const float*)d_in[10];
    const float* enc2_g  = (const float*)d_in[11];
    const float* enc2_bt = (const float*)d_in[12];
    const float* enc3_w  = (const float*)d_in[13];
    const float* enc3_b  = (const float*)d_in[14];
    const float* codebook= (const float*)d_in[15];
    const float* dec0_w  = (const float*)d_in[16];
    const float* dec0_b  = (const float*)d_in[17];
    const float* dec1_w  = (const float*)d_in[18];
    const float* dec1_b  = (const float*)d_in[19];
    const float* dec1_g  = (const float*)d_in[20];
    const float* dec1_bt = (const float*)d_in[21];
    const float* dec2_w  = (const float*)d_in[22];
    const float* dec2_b  = (const float*)d_in[23];
    const float* dec2_g  = (const float*)d_in[24];
    const float* dec2_bt = (const float*)d_in[25];
    const float* dec3_w  = (const float*)d_in[26];
    const float* dec3_b  = (const float*)d_in[27];

    float* out = (float*)d_out;

    float *bufA, *bufB, *bufC, *bufZ, *bufQ;
    cudaGetSymbolAddress((void**)&bufA, g_bufA);
    cudaGetSymbolAddress((void**)&bufB, g_bufB);
    cudaGetSymbolAddress((void**)&bufC, g_bufC);
    cudaGetSymbolAddress((void**)&bufZ, g_bufZ);
    cudaGetSymbolAddress((void**)&bufQ, g_bufQ);

    // ---- encoder ----
    conv_s2_big<<<dim3(128, 1, 16), 256>>>(x, enc0_w, enc0_b, bufA, 3, 128, 256, 256);
    gn_stats_kernel<<<512, 256>>>(bufA, 4 * 128 * 128);
    gn_apply_silu_kernel<<<32768, 256>>>(bufA, enc0_g, enc0_bt, 128, 128 * 128, 4);

    conv_s2_big<<<dim3(32, 2, 16), 256>>>(bufA, enc1_w, enc1_b, bufB, 128, 256, 128, 128);
    gn_stats_kernel<<<512, 256>>>(bufB, 8 * 64 * 64);
    gn_apply_silu_kernel<<<16384, 256>>>(bufB, enc1_g, enc1_bt, 256, 64 * 64, 8);

    conv_s2_big<<<dim3(8, 4, 16), 256>>>(bufB, enc2_w, enc2_b, bufC, 256, 512, 64, 64);
    gn_stats_kernel<<<512, 256>>>(bufC, 16 * 32 * 32);
    gn_apply_silu_kernel<<<8192, 256>>>(bufC, enc2_g, enc2_bt, 512, 32 * 32, 16);

    conv1x1_enc3_kernel<<<64, 256>>>(bufC, enc3_w, enc3_b, bufZ);

    // ---- VQ ----
    vq_kernel<<<64, 256>>>(bufZ, codebook, bufQ, out + 3145728, out + 3670016);

    // ---- decoder ----
    conv1x1_dec0_kernel<<<dim3(256, 8), 256>>>(bufQ, dec0_w, dec0_b, bufC);

    convt_big<<<dim3(32, 2, 16), 256>>>(bufC, dec1_w, dec1_b, bufB, 512, 256, 32, 32);
    gn_stats_kernel<<<512, 256>>>(bufB, 8 * 64 * 64);
    gn_apply_silu_kernel<<<16384, 256>>>(bufB, dec1_g, dec1_bt, 256, 64 * 64, 8);

    convt_big<<<dim3(128, 1, 16), 256>>>(bufB, dec2_w, dec2_b, bufA, 256, 128, 64, 64);
    gn_stats_kernel<<<512, 256>>>(bufA, 4 * 128 * 128);
    gn_apply_silu_kernel<<<32768, 256>>>(bufA, dec2_g, dec2_bt, 128, 128 * 128, 4);

    convt_final_kernel<<<dim3(256, 16), 256>>>(bufA, dec3_w, dec3_b, out);
}

// round 8
// speedup vs baseline: 1.2186x; 1.2186x over previous
#include <cuda_runtime.h>
#include <math.h>

// ---------------- scratch (device globals) ----------------
__device__ float g_bufA[33554432];  // 16x128x128x128
__device__ float g_bufB[16777216];  // 16x256x64x64
__device__ float g_bufC[8388608];   // 16x512x32x32
__device__ float g_bufZ[524288];    // 16x32x32x32
__device__ float g_bufQ[524288];
__device__ float g_mean[512];
__device__ float g_rstd[512];

// packed f32x2 FMA: acc.x += a.x*b.x ; acc.y += a.y*b.y
__device__ __forceinline__ void ffma2(float2& acc, float2 a, float2 b) {
    unsigned long long ua = *reinterpret_cast<unsigned long long*>(&a);
    unsigned long long ub = *reinterpret_cast<unsigned long long*>(&b);
    unsigned long long uc = *reinterpret_cast<unsigned long long*>(&acc);
    asm("fma.rn.f32x2 %0, %1, %2, %0;" : "+l"(uc) : "l"(ua), "l"(ub));
    acc = *reinterpret_cast<float2*>(&uc);
}

// =============== stride-2 4x4 conv pad 1: 128 co x (8 rows x 16 cols) px per block ===============
// thread: colx = tid&15 (px column), cog = tid>>4 (8 co). acc = 8 rows x 4 co-pairs (f32x2).
// __launch_bounds__(256,2): cap regs at 128 so 2 CTAs/SM are resident (occupancy fix).
__global__ __launch_bounds__(256, 2) void conv_s2_big(
    const float* __restrict__ in, const float* __restrict__ w,
    const float* __restrict__ bias, float* __restrict__ out,
    int Cin, int Cout, int Hin, int Win)
{
    const int Hout = Hin >> 1, Wout = Win >> 1;
    const int tilesX = Wout >> 4;
    const int oh0 = (blockIdx.x / tilesX) << 3;
    const int ow0 = (blockIdx.x % tilesX) << 4;
    const int cob = blockIdx.y << 7;
    const int n = blockIdx.z;

    __shared__ float P[4][18][36];                    // 18 rows x 34 cols used
    __shared__ __align__(16) float Wt[4][16][132];    // [c][khw][co], row 528B (16B mult)

    const int tid = threadIdx.x;
    const int colx = tid & 15;
    const int cog  = tid >> 4;

    float2 acc[8][4];
#pragma unroll
    for (int r = 0; r < 8; ++r)
#pragma unroll
        for (int k = 0; k < 4; ++k) acc[r][k] = make_float2(0.f, 0.f);

    const float* inb = in + (size_t)n * Cin * Hin * Win;

    for (int c0 = 0; c0 < Cin; c0 += 4) {
        // weights: [c][khw][co]
        for (int idx = tid; idx < 8192; idx += 256) {
            int khw = idx & 15, r = idx >> 4;
            int co = r & 127, c = r >> 7;
            float v = 0.f;
            if (c0 + c < Cin)
                v = w[((size_t)(cob + co) * Cin + c0 + c) * 16 + khw];
            Wt[c][khw][co] = v;
        }
        // input patch: 4 ch x 18 x 34
        for (int idx = tid; idx < 2448; idx += 256) {
            int c = idx / 612, r = idx - c * 612;
            int pr = r / 34, pc = r - pr * 34;
            int ih = 2 * oh0 - 1 + pr, iw = 2 * ow0 - 1 + pc;
            float v = 0.f;
            if (c0 + c < Cin && (unsigned)ih < (unsigned)Hin && (unsigned)iw < (unsigned)Win)
                v = inb[((size_t)(c0 + c) * Hin + ih) * Win + iw];
            P[c][pr][pc] = v;
        }
        __syncthreads();

#pragma unroll 1
        for (int c = 0; c < 4; ++c) {
#pragma unroll
            for (int kh = 0; kh < 4; ++kh) {
#pragma unroll
                for (int kw = 0; kw < 4; ++kw) {
                    const float4* wr = reinterpret_cast<const float4*>(&Wt[c][(kh << 2) + kw][cog << 3]);
                    float4 wA = wr[0], wB = wr[1];
                    float2 wp0 = make_float2(wA.x, wA.y);
                    float2 wp1 = make_float2(wA.z, wA.w);
                    float2 wp2 = make_float2(wB.x, wB.y);
                    float2 wp3 = make_float2(wB.z, wB.w);
#pragma unroll
                    for (int r = 0; r < 8; ++r) {
                        float a = P[c][2 * r + kh][2 * colx + kw];
                        float2 a2 = make_float2(a, a);
                        ffma2(acc[r][0], a2, wp0);
                        ffma2(acc[r][1], a2, wp1);
                        ffma2(acc[r][2], a2, wp2);
                        ffma2(acc[r][3], a2, wp3);
                    }
                }
            }
        }
        __syncthreads();
    }

#pragma unroll
    for (int kp = 0; kp < 4; ++kp) {
        int co = cob + (cog << 3) + (kp << 1);
        float b0 = bias[co], b1 = bias[co + 1];
        float* o0 = out + (((size_t)n * Cout + co) * Hout + oh0) * Wout + ow0 + colx;
        float* o1 = o0 + (size_t)Hout * Wout;
#pragma unroll
        for (int r = 0; r < 8; ++r) {
            o0[(size_t)r * Wout] = acc[r][kp].x + b0;
            o1[(size_t)r * Wout] = acc[r][kp].y + b1;
        }
    }
}

// =============== transposed conv k4 s2 p1: 128 co x (8 rows x 16 cols) out px per block ===============
// acc pairs over (even,odd) output rows; weights pre-paired (kh_even, kh_odd) per tap.
__global__ __launch_bounds__(256, 2) void convt_big(
    const float* __restrict__ in, const float* __restrict__ w,
    const float* __restrict__ bias, float* __restrict__ out,
    int Cin, int Cout, int Hin, int Win)
{
    const int Hout = Hin << 1, Wout = Win << 1;
    const int tilesX = Wout >> 4;
    const int oh0 = (blockIdx.x / tilesX) << 3;
    const int ow0 = (blockIdx.x % tilesX) << 4;
    const int cob = blockIdx.y << 7;
    const int n = blockIdx.z;

    __shared__ float P[4][6][12];                          // 6 rows x 10 cols used
    __shared__ __align__(16) float2 Wp[4][2][2][2][130];   // [c][dh][dw][pw][co] 128 co + pad

    const int tid = threadIdx.x;
    const int colx = tid & 15;
    const int cog  = tid >> 4;
    const int pw = colx & 1;
    const int iwl0 = (colx + pw) >> 1;
    const int r0 = (oh0 >> 1) - 1;
    const int col0 = (ow0 >> 1) - 1;

    float2 acc[4][8];  // [row-pair t][co k]
#pragma unroll
    for (int t = 0; t < 4; ++t)
#pragma unroll
        for (int k = 0; k < 8; ++k) acc[t][k] = make_float2(0.f, 0.f);

    const float* inb = in + (size_t)n * Cin * Hin * Win;

    for (int c0 = 0; c0 < Cin; c0 += 4) {
        // pre-paired weights: (kh=2dh, kh=2dh+1) at kw=2dw+pw
        for (int idx = tid; idx < 4096; idx += 256) {
            int p = idx & 7;
            int co = (idx >> 3) & 127;
            int c = idx >> 10;
            int dh = p >> 2, dw = (p >> 1) & 1, pww = p & 1;
            size_t base = ((size_t)(cob + co) * Cin + c0 + c) * 16 + (dh << 3) + (dw << 1) + pww;
            Wp[c][dh][dw][pww][co] = make_float2(w[base], w[base + 4]);
        }
        // input patch 4 ch x 6 x 10
        for (int idx = tid; idx < 240; idx += 256) {
            int c = idx / 60, r = idx - c * 60;
            int pr = r / 10, pc = r - pr * 10;
            int ih = r0 + pr, iw = col0 + pc;
            float v = 0.f;
            if ((unsigned)ih < (unsigned)Hin && (unsigned)iw < (unsigned)Win)
                v = inb[((size_t)(c0 + c) * Hin + ih) * Win + iw];
            P[c][pr][pc] = v;
        }
        __syncthreads();

#pragma unroll 1
        for (int c = 0; c < 4; ++c) {
#pragma unroll
            for (int dh = 0; dh < 2; ++dh) {
#pragma unroll
                for (int dw = 0; dw < 2; ++dw) {
                    float a[5];
#pragma unroll
                    for (int t = 0; t < 5; ++t)
                        a[t] = P[c][t + dh][iwl0 + dw];
                    const float4* wr = reinterpret_cast<const float4*>(&Wp[c][dh][dw][pw][cog << 3]);
#pragma unroll
                    for (int q = 0; q < 4; ++q) {
                        float4 v = wr[q];
                        float2 w0 = make_float2(v.x, v.y);
                        float2 w1 = make_float2(v.z, v.w);
#pragma unroll
                        for (int t = 0; t < 4; ++t) {
                            float2 ap = make_float2(a[t], a[t + 1]);
                            ffma2(acc[t][2 * q],     ap, w0);
                            ffma2(acc[t][2 * q + 1], ap, w1);
                        }
                    }
                }
            }
        }
        __syncthreads();
    }

#pragma unroll
    for (int k = 0; k < 8; ++k) {
        int co = cob + (cog << 3) + k;
        float b = bias[co];
        float* ob = out + (((size_t)n * Cout + co) * Hout + oh0) * Wout + ow0 + colx;
#pragma unroll
        for (int t = 0; t < 4; ++t) {
            ob[(size_t)(2 * t) * Wout]     = acc[t][k].x + b;
            ob[(size_t)(2 * t + 1) * Wout] = acc[t][k].y + b;
        }
    }
}

// =============== final transposed conv 128->3 + tanh ===============
__global__ __launch_bounds__(256) void convt_final_kernel(
    const float* __restrict__ in, const float* __restrict__ w,
    const float* __restrict__ bias, float* __restrict__ out)
{
    const int n = blockIdx.y;
    const int oh0 = (blockIdx.x >> 4) << 4;
    const int ow0 = (blockIdx.x & 15) << 4;
    __shared__ float P[8][10][11];
    __shared__ float Wsm[8][3][17];
    const int tid = threadIdx.x;
    const int py = tid >> 4, px = tid & 15;
    const int ph = py & 1, pw = px & 1;
    const int ihl0 = (py + ph) >> 1, iwl0 = (px + pw) >> 1;
    const int r0 = (oh0 >> 1) - 1, col0 = (ow0 >> 1) - 1;
    float acc0 = 0.f, acc1 = 0.f, acc2 = 0.f;
    const float* inb = in + ((size_t)n << 21);

    for (int c0 = 0; c0 < 128; c0 += 8) {
        for (int idx = tid; idx < 800; idx += 256) {
            int c = idx / 100, r = idx - c * 100;
            int rr = r / 10, cc = r - rr * 10;
            int ih = r0 + rr, iw = col0 + cc;
            float v = 0.f;
            if ((unsigned)ih < 128u && (unsigned)iw < 128u)
                v = inb[((size_t)(c0 + c) << 14) + (ih << 7) + iw];
            P[c][rr][cc] = v;
        }
        for (int idx = tid; idx < 384; idx += 256) {
            int c = idx / 48, r = idx - c * 48;
            int co = r >> 4, khw = r & 15;
            Wsm[c][co][khw] = w[((size_t)co * 128 + c0 + c) * 16 + khw];
        }
        __syncthreads();
#pragma unroll
        for (int c = 0; c < 8; ++c) {
#pragma unroll
            for (int dh = 0; dh < 2; ++dh) {
#pragma unroll
                for (int dw = 0; dw < 2; ++dw) {
                    float a = P[c][ihl0 + dh][iwl0 + dw];
                    int khw = ((ph + (dh << 1)) << 2) + pw + (dw << 1);
                    acc0 += a * Wsm[c][0][khw];
                    acc1 += a * Wsm[c][1][khw];
                    acc2 += a * Wsm[c][2][khw];
                }
            }
        }
        __syncthreads();
    }
    const int oh = oh0 + py, ow = ow0 + px;
    size_t base = ((size_t)n * 3) * 65536 + ((size_t)oh << 8) + ow;
    out[base]          = tanhf(acc0 + bias[0]);
    out[base + 65536]  = tanhf(acc1 + bias[1]);
    out[base + 131072] = tanhf(acc2 + bias[2]);
}

// =============== group-norm stats ===============
__global__ __launch_bounds__(256) void gn_stats_kernel(const float* __restrict__ x, int span)
{
    const float* p = x + (size_t)blockIdx.x * span;
    float s = 0.f, ss = 0.f;
    for (int i = threadIdx.x; i < span; i += 256) {
        float v = p[i];
        s += v; ss += v * v;
    }
#pragma unroll
    for (int o = 16; o; o >>= 1) {
        s  += __shfl_down_sync(0xffffffffu, s, o);
        ss += __shfl_down_sync(0xffffffffu, ss, o);
    }
    __shared__ float as[8], bs[8];
    int wi = threadIdx.x >> 5, l = threadIdx.x & 31;
    if (l == 0) { as[wi] = s; bs[wi] = ss; }
    __syncthreads();
    if (threadIdx.x == 0) {
        s = 0.f; ss = 0.f;
#pragma unroll
        for (int i = 0; i < 8; ++i) { s += as[i]; ss += bs[i]; }
        float m = s / (float)span;
        float var = ss / (float)span - m * m;
        g_mean[blockIdx.x] = m;
        g_rstd[blockIdx.x] = rsqrtf(var + 1e-5f);
    }
}

// =============== fused GN apply + SiLU ===============
__global__ __launch_bounds__(256) void gn_apply_silu_kernel(
    float* __restrict__ x, const float* __restrict__ gamma, const float* __restrict__ beta,
    int C, int HW, int cpg)
{
    size_t i = (size_t)blockIdx.x * 256 + threadIdx.x;
    size_t e = i * 4;
    size_t ch = e / (size_t)HW;
    int c = (int)(ch % C);
    int n = (int)(ch / C);
    int gi = n * 32 + c / cpg;
    float m = g_mean[gi], r = g_rstd[gi];
    float ga = gamma[c], be = beta[c];
    float4 v = *reinterpret_cast<float4*>(x + e);
    float y;
    y = (v.x - m) * r * ga + be; v.x = y / (1.f + expf(-y));
    y = (v.y - m) * r * ga + be; v.y = y / (1.f + expf(-y));
    y = (v.z - m) * r * ga + be; v.z = y / (1.f + expf(-y));
    y = (v.w - m) * r * ga + be; v.w = y / (1.f + expf(-y));
    *reinterpret_cast<float4*>(x + e) = v;
}

// =============== 1x1 conv 512->32 ===============
__global__ __launch_bounds__(256) void conv1x1_enc3_kernel(
    const float* __restrict__ in, const float* __restrict__ w,
    const float* __restrict__ bias, float* __restrict__ out)
{
    const int t = blockIdx.x * 256 + threadIdx.x;
    const int n = t >> 10, pix = t & 1023;
    __shared__ float wsm[128][33];
    float acc[32];
#pragma unroll
    for (int k = 0; k < 32; ++k) acc[k] = 0.f;
    for (int c0 = 0; c0 < 512; c0 += 128) {
        __syncthreads();
        for (int idx = threadIdx.x; idx < 4096; idx += 256) {
            int co = idx >> 7, cc = idx & 127;
            wsm[cc][co] = w[(size_t)co * 512 + c0 + cc];
        }
        __syncthreads();
        for (int cc = 0; cc < 128; ++cc) {
            float a = in[(((size_t)n * 512 + c0 + cc) << 10) + pix];
#pragma unroll
            for (int k = 0; k < 32; ++k) acc[k] += a * wsm[cc][k];
        }
    }
#pragma unroll
    for (int k = 0; k < 32; ++k)
        out[(((size_t)n * 32 + k) << 10) + pix] = acc[k] + bias[k];
}

// =============== vector quantization ===============
__global__ __launch_bounds__(256) void vq_kernel(
    const float* __restrict__ z, const float* __restrict__ cbk,
    float* __restrict__ q, float* __restrict__ outq, float* __restrict__ outidx)
{
    const int m = blockIdx.x * 256 + threadIdx.x;
    float v[32];
#pragma unroll
    for (int j = 0; j < 32; ++j) v[j] = z[(size_t)m * 32 + j];
    __shared__ float csm[128][33];
    __shared__ float c2sm[128];
    float best = 3.4e38f;
    int bi = 0;
    for (int k0 = 0; k0 < 1024; k0 += 128) {
        __syncthreads();
        for (int idx = threadIdx.x; idx < 4096; idx += 256)
            csm[idx >> 5][idx & 31] = cbk[(size_t)k0 * 32 + idx];
        __syncthreads();
        if (threadIdx.x < 128) {
            float s = 0.f;
#pragma unroll
            for (int j = 0; j < 32; ++j) { float c = csm[threadIdx.x][j]; s += c * c; }
            c2sm[threadIdx.x] = s;
        }
        __syncthreads();
        for (int k = 0; k < 128; ++k) {
            float dot = 0.f;
#pragma unroll
            for (int j = 0; j < 32; ++j) dot += v[j] * csm[k][j];
            float d = c2sm[k] - 2.f * dot;
            if (d < best) { best = d; bi = k0 + k; }
        }
    }
#pragma unroll
    for (int j = 0; j < 32; ++j) {
        float qv = cbk[(size_t)bi * 32 + j];
        q[(size_t)m * 32 + j] = qv;
        outq[(size_t)m * 32 + j] = qv;
    }
    outidx[m] = (float)bi;
}

// =============== 1x1 conv 32->512 ===============
__global__ __launch_bounds__(256) void conv1x1_dec0_kernel(
    const float* __restrict__ q, const float* __restrict__ w,
    const float* __restrict__ bias, float* __restrict__ out)
{
    const int n = blockIdx.x >> 4;
    const int pix0 = (blockIdx.x & 15) << 6;
    const int cob = blockIdx.y << 6;
    __shared__ float qsm[32][64];
    __shared__ float wsm[32][65];
    const int tid = threadIdx.x;
    const int p = tid & 63, cg = tid >> 6;
    for (int idx = tid; idx < 2048; idx += 256) {
        int ci = idx >> 6, pp = idx & 63;
        qsm[ci][pp] = q[(((size_t)n * 32 + ci) << 10) + pix0 + pp];
    }
    for (int idx = tid; idx < 2048; idx += 256) {
        int co = idx >> 5, ci = idx & 31;
        wsm[ci][co] = w[((size_t)(cob + co) << 5) + ci];
    }
    __syncthreads();
    float acc[16];
#pragma unroll
    for (int k = 0; k < 16; ++k) acc[k] = 0.f;
#pragma unroll
    for (int ci = 0; ci < 32; ++ci) {
        float a = qsm[ci][p];
#pragma unroll
        for (int k = 0; k < 16; ++k)
            acc[k] += a * wsm[ci][(cg << 4) + k];
    }
#pragma unroll
    for (int k = 0; k < 16; ++k) {
        int co = cob + (cg << 4) + k;
        out[(((size_t)n * 512 + co) << 10) + pix0 + p] = acc[k] + bias[co];
    }
}

// =================================================================================
extern "C" void kernel_launch(void* const* d_in, const int* in_sizes, int n_in,
                              void* d_out, int out_size)
{
    const float* x       = (const float*)d_in[0];
    const float* enc0_w  = (const float*)d_in[1];
    const float* enc0_b  = (const float*)d_in[2];
    const float* enc0_g  = (const float*)d_in[3];
    const float* enc0_bt = (const float*)d_in[4];
    const float* enc1_w  = (const float*)d_in[5];
    const float* enc1_b  = (const float*)d_in[6];
    const float* enc1_g  = (const float*)d_in[7];
    const float* enc1_bt = (const float*)d_in[8];
    const float* enc2_w  = (const float*)d_in[9];
    const float* enc2_b  = (const float*)d_in[10];
    const float* enc2_g  = (const float*)d_in[11];
    const float* enc2_bt = (const float*)d_in[12];
    const float* enc3_w  = (const float*)d_in[13];
    const float* enc3_b  = (const float*)d_in[14];
    const float* codebook= (const float*)d_in[15];
    const float* dec0_w  = (const float*)d_in[16];
    const float* dec0_b  = (const float*)d_in[17];
    const float* dec1_w  = (const float*)d_in[18];
    const float* dec1_b  = (const float*)d_in[19];
    const float* dec1_g  = (const float*)d_in[20];
    const float* dec1_bt = (const float*)d_in[21];
    const float* dec2_w  = (const float*)d_in[22];
    const float* dec2_b  = (const float*)d_in[23];
    const float* dec2_g  = (const float*)d_in[24];
    const float* dec2_bt = (const float*)d_in[25];
    const float* dec3_w  = (const float*)d_in[26];
    const float* dec3_b  = (const float*)d_in[27];

    float* out = (float*)d_out;

    float *bufA, *bufB, *bufC, *bufZ, *bufQ;
    cudaGetSymbolAddress((void**)&bufA, g_bufA);
    cudaGetSymbolAddress((void**)&bufB, g_bufB);
    cudaGetSymbolAddress((void**)&bufC, g_bufC);
    cudaGetSymbolAddress((void**)&bufZ, g_bufZ);
    cudaGetSymbolAddress((void**)&bufQ, g_bufQ);

    // ---- encoder ----
    conv_s2_big<<<dim3(128, 1, 16), 256>>>(x, enc0_w, enc0_b, bufA, 3, 128, 256, 256);
    gn_stats_kernel<<<512, 256>>>(bufA, 4 * 128 * 128);
    gn_apply_silu_kernel<<<32768, 256>>>(bufA, enc0_g, enc0_bt, 128, 128 * 128, 4);

    conv_s2_big<<<dim3(32, 2, 16), 256>>>(bufA, enc1_w, enc1_b, bufB, 128, 256, 128, 128);
    gn_stats_kernel<<<512, 256>>>(bufB, 8 * 64 * 64);
    gn_apply_silu_kernel<<<16384, 256>>>(bufB, enc1_g, enc1_bt, 256, 64 * 64, 8);

    conv_s2_big<<<dim3(8, 4, 16), 256>>>(bufB, enc2_w, enc2_b, bufC, 256, 512, 64, 64);
    gn_stats_kernel<<<512, 256>>>(bufC, 16 * 32 * 32);
    gn_apply_silu_kernel<<<8192, 256>>>(bufC, enc2_g, enc2_bt, 512, 32 * 32, 16);

    conv1x1_enc3_kernel<<<64, 256>>>(bufC, enc3_w, enc3_b, bufZ);

    // ---- VQ ----
    vq_kernel<<<64, 256>>>(bufZ, codebook, bufQ, out + 3145728, out + 3670016);

    // ---- decoder ----
    conv1x1_dec0_kernel<<<dim3(256, 8), 256>>>(bufQ, dec0_w, dec0_b, bufC);

    convt_big<<<dim3(32, 2, 16), 256>>>(bufC, dec1_w, dec1_b, bufB, 512, 256, 32, 32);
    gn_stats_kernel<<<512, 256>>>(bufB, 8 * 64 * 64);
    gn_apply_silu_kernel<<<16384, 256>>>(bufB, dec1_g, dec1_bt, 256, 64 * 64, 8);

    convt_big<<<dim3(128, 1, 16), 256>>>(bufB, dec2_w, dec2_b, bufA, 256, 128, 64, 64);
    gn_stats_kernel<<<512, 256>>>(bufA, 4 * 128 * 128);
    gn_apply_silu_kernel<<<32768, 256>>>(bufA, dec2_g, dec2_bt, 128, 128 * 128, 4);

    convt_final_kernel<<<dim3(256, 16), 256>>>(bufA, dec3_w, dec3_b, out);
}

// round 9
// speedup vs baseline: 1.2238x; 1.0043x over previous
#include <cuda_runtime.h>
#include <math.h>

// ---------------- scratch (device globals) ----------------
__device__ float g_bufA[33554432];  // 16x128x128x128
__device__ float g_bufB[16777216];  // 16x256x64x64
__device__ float g_bufC[8388608];   // 16x512x32x32
__device__ float g_bufZ[524288];    // 16x32x32x32
__device__ float g_bufQ[524288];
__device__ float g_mean[512];
__device__ float g_rstd[512];

// packed f32x2 FMA: acc.x += a.x*b.x ; acc.y += a.y*b.y
__device__ __forceinline__ void ffma2(float2& acc, float2 a, float2 b) {
    unsigned long long ua = *reinterpret_cast<unsigned long long*>(&a);
    unsigned long long ub = *reinterpret_cast<unsigned long long*>(&b);
    unsigned long long uc = *reinterpret_cast<unsigned long long*>(&acc);
    asm("fma.rn.f32x2 %0, %1, %2, %0;" : "+l"(uc) : "l"(ua), "l"(ub));
    acc = *reinterpret_cast<float2*>(&uc);
}

// =============== stride-2 4x4 conv pad 1: 128 co x (8 rows x 16 cols) px per block ===============
// thread: colx = tid&15 (px column), cog = tid>>4 (8 co). acc = 8 rows x 4 co-pairs (f32x2).
// Inner loop: float2 activation loads (one LDS.64 covers taps kw,kw+1) to halve LDS+IMAD count.
__global__ __launch_bounds__(256, 2) void conv_s2_big(
    const float* __restrict__ in, const float* __restrict__ w,
    const float* __restrict__ bias, float* __restrict__ out,
    int Cin, int Cout, int Hin, int Win)
{
    const int Hout = Hin >> 1, Wout = Win >> 1;
    const int tilesX = Wout >> 4;
    const int oh0 = (blockIdx.x / tilesX) << 3;
    const int ow0 = (blockIdx.x % tilesX) << 4;
    const int cob = blockIdx.y << 7;
    const int n = blockIdx.z;

    __shared__ __align__(8)  float P[4][18][36];      // 18 rows x 34 cols used
    __shared__ __align__(16) float Wt[4][16][132];    // [c][khw][co], row 528B (16B mult)

    const int tid = threadIdx.x;
    const int colx = tid & 15;
    const int cog  = tid >> 4;

    float2 acc[8][4];
#pragma unroll
    for (int r = 0; r < 8; ++r)
#pragma unroll
        for (int k = 0; k < 4; ++k) acc[r][k] = make_float2(0.f, 0.f);

    const float* inb = in + (size_t)n * Cin * Hin * Win;

    for (int c0 = 0; c0 < Cin; c0 += 4) {
        // weights: [c][khw][co]
        for (int idx = tid; idx < 8192; idx += 256) {
            int khw = idx & 15, r = idx >> 4;
            int co = r & 127, c = r >> 7;
            float v = 0.f;
            if (c0 + c < Cin)
                v = w[((size_t)(cob + co) * Cin + c0 + c) * 16 + khw];
            Wt[c][khw][co] = v;
        }
        // input patch: 4 ch x 18 x 34
        for (int idx = tid; idx < 2448; idx += 256) {
            int c = idx / 612, r = idx - c * 612;
            int pr = r / 34, pc = r - pr * 34;
            int ih = 2 * oh0 - 1 + pr, iw = 2 * ow0 - 1 + pc;
            float v = 0.f;
            if (c0 + c < Cin && (unsigned)ih < (unsigned)Hin && (unsigned)iw < (unsigned)Win)
                v = inb[((size_t)(c0 + c) * Hin + ih) * Win + iw];
            P[c][pr][pc] = v;
        }
        __syncthreads();

#pragma unroll 1
        for (int c = 0; c < 4; ++c) {
#pragma unroll
            for (int kh = 0; kh < 4; ++kh) {
#pragma unroll
                for (int kwp = 0; kwp < 2; ++kwp) {
                    // activation pairs: (kw=2kwp, kw=2kwp+1), 8B-aligned float2 loads
                    float2 av[8];
#pragma unroll
                    for (int r = 0; r < 8; ++r)
                        av[r] = *reinterpret_cast<const float2*>(&P[c][2 * r + kh][2 * colx + 2 * kwp]);

                    const int khw0 = (kh << 2) + 2 * kwp;
                    const float4* w0 = reinterpret_cast<const float4*>(&Wt[c][khw0][cog << 3]);
                    const float4* w1 = reinterpret_cast<const float4*>(&Wt[c][khw0 + 1][cog << 3]);
                    float4 wA0 = w0[0], wB0 = w0[1];
                    float4 wA1 = w1[0], wB1 = w1[1];
                    float2 p00 = make_float2(wA0.x, wA0.y), p01 = make_float2(wA0.z, wA0.w);
                    float2 p02 = make_float2(wB0.x, wB0.y), p03 = make_float2(wB0.z, wB0.w);
                    float2 p10 = make_float2(wA1.x, wA1.y), p11 = make_float2(wA1.z, wA1.w);
                    float2 p12 = make_float2(wB1.x, wB1.y), p13 = make_float2(wB1.z, wB1.w);
#pragma unroll
                    for (int r = 0; r < 8; ++r) {
                        float2 ax = make_float2(av[r].x, av[r].x);
                        float2 ay = make_float2(av[r].y, av[r].y);
                        ffma2(acc[r][0], ax, p00);
                        ffma2(acc[r][1], ax, p01);
                        ffma2(acc[r][2], ax, p02);
                        ffma2(acc[r][3], ax, p03);
                        ffma2(acc[r][0], ay, p10);
                        ffma2(acc[r][1], ay, p11);
                        ffma2(acc[r][2], ay, p12);
                        ffma2(acc[r][3], ay, p13);
                    }
                }
            }
        }
        __syncthreads();
    }

#pragma unroll
    for (int kp = 0; kp < 4; ++kp) {
        int co = cob + (cog << 3) + (kp << 1);
        float b0 = bias[co], b1 = bias[co + 1];
        float* o0 = out + (((size_t)n * Cout + co) * Hout + oh0) * Wout + ow0 + colx;
        float* o1 = o0 + (size_t)Hout * Wout;
#pragma unroll
        for (int r = 0; r < 8; ++r) {
            o0[(size_t)r * Wout] = acc[r][kp].x + b0;
            o1[(size_t)r * Wout] = acc[r][kp].y + b1;
        }
    }
}

// =============== transposed conv k4 s2 p1: 128 co x (8 rows x 16 cols) out px per block ===============
// acc pairs over (even,odd) output rows; weights pre-paired (kh_even, kh_odd) per tap.
__global__ __launch_bounds__(256, 2) void convt_big(
    const float* __restrict__ in, const float* __restrict__ w,
    const float* __restrict__ bias, float* __restrict__ out,
    int Cin, int Cout, int Hin, int Win)
{
    const int Hout = Hin << 1, Wout = Win << 1;
    const int tilesX = Wout >> 4;
    const int oh0 = (blockIdx.x / tilesX) << 3;
    const int ow0 = (blockIdx.x % tilesX) << 4;
    const int cob = blockIdx.y << 7;
    const int n = blockIdx.z;

    __shared__ float P[4][6][12];                          // 6 rows x 10 cols used
    __shared__ __align__(16) float2 Wp[4][2][2][2][130];   // [c][dh][dw][pw][co] 128 co + pad

    const int tid = threadIdx.x;
    const int colx = tid & 15;
    const int cog  = tid >> 4;
    const int pw = colx & 1;
    const int iwl0 = (colx + pw) >> 1;
    const int r0 = (oh0 >> 1) - 1;
    const int col0 = (ow0 >> 1) - 1;

    float2 acc[4][8];  // [row-pair t][co k]
#pragma unroll
    for (int t = 0; t < 4; ++t)
#pragma unroll
        for (int k = 0; k < 8; ++k) acc[t][k] = make_float2(0.f, 0.f);

    const float* inb = in + (size_t)n * Cin * Hin * Win;

    for (int c0 = 0; c0 < Cin; c0 += 4) {
        // pre-paired weights: (kh=2dh, kh=2dh+1) at kw=2dw+pw
        for (int idx = tid; idx < 4096; idx += 256) {
            int p = idx & 7;
            int co = (idx >> 3) & 127;
            int c = idx >> 10;
            int dh = p >> 2, dw = (p >> 1) & 1, pww = p & 1;
            size_t base = ((size_t)(cob + co) * Cin + c0 + c) * 16 + (dh << 3) + (dw << 1) + pww;
            Wp[c][dh][dw][pww][co] = make_float2(w[base], w[base + 4]);
        }
        // input patch 4 ch x 6 x 10
        for (int idx = tid; idx < 240; idx += 256) {
            int c = idx / 60, r = idx - c * 60;
            int pr = r / 10, pc = r - pr * 10;
            int ih = r0 + pr, iw = col0 + pc;
            float v = 0.f;
            if ((unsigned)ih < (unsigned)Hin && (unsigned)iw < (unsigned)Win)
                v = inb[((size_t)(c0 + c) * Hin + ih) * Win + iw];
            P[c][pr][pc] = v;
        }
        __syncthreads();

#pragma unroll 1
        for (int c = 0; c < 4; ++c) {
#pragma unroll
            for (int dh = 0; dh < 2; ++dh) {
#pragma unroll
                for (int dw = 0; dw < 2; ++dw) {
                    float a[5];
#pragma unroll
                    for (int t = 0; t < 5; ++t)
                        a[t] = P[c][t + dh][iwl0 + dw];
                    const float4* wr = reinterpret_cast<const float4*>(&Wp[c][dh][dw][pw][cog << 3]);
#pragma unroll
                    for (int q = 0; q < 4; ++q) {
                        float4 v = wr[q];
                        float2 w0 = make_float2(v.x, v.y);
                        float2 w1 = make_float2(v.z, v.w);
#pragma unroll
                        for (int t = 0; t < 4; ++t) {
                            float2 ap = make_float2(a[t], a[t + 1]);
                            ffma2(acc[t][2 * q],     ap, w0);
                            ffma2(acc[t][2 * q + 1], ap, w1);
                        }
                    }
                }
            }
        }
        __syncthreads();
    }

#pragma unroll
    for (int k = 0; k < 8; ++k) {
        int co = cob + (cog << 3) + k;
        float b = bias[co];
        float* ob = out + (((size_t)n * Cout + co) * Hout + oh0) * Wout + ow0 + colx;
#pragma unroll
        for (int t = 0; t < 4; ++t) {
            ob[(size_t)(2 * t) * Wout]     = acc[t][k].x + b;
            ob[(size_t)(2 * t + 1) * Wout] = acc[t][k].y + b;
        }
    }
}

// =============== final transposed conv 128->3 + tanh ===============
__global__ __launch_bounds__(256) void convt_final_kernel(
    const float* __restrict__ in, const float* __restrict__ w,
    const float* __restrict__ bias, float* __restrict__ out)
{
    const int n = blockIdx.y;
    const int oh0 = (blockIdx.x >> 4) << 4;
    const int ow0 = (blockIdx.x & 15) << 4;
    __shared__ float P[8][10][11];
    __shared__ float Wsm[8][3][17];
    const int tid = threadIdx.x;
    const int py = tid >> 4, px = tid & 15;
    const int ph = py & 1, pw = px & 1;
    const int ihl0 = (py + ph) >> 1, iwl0 = (px + pw) >> 1;
    const int r0 = (oh0 >> 1) - 1, col0 = (ow0 >> 1) - 1;
    float acc0 = 0.f, acc1 = 0.f, acc2 = 0.f;
    const float* inb = in + ((size_t)n << 21);

    for (int c0 = 0; c0 < 128; c0 += 8) {
        for (int idx = tid; idx < 800; idx += 256) {
            int c = idx / 100, r = idx - c * 100;
            int rr = r / 10, cc = r - rr * 10;
            int ih = r0 + rr, iw = col0 + cc;
            float v = 0.f;
            if ((unsigned)ih < 128u && (unsigned)iw < 128u)
                v = inb[((size_t)(c0 + c) << 14) + (ih << 7) + iw];
            P[c][rr][cc] = v;
        }
        for (int idx = tid; idx < 384; idx += 256) {
            int c = idx / 48, r = idx - c * 48;
            int co = r >> 4, khw = r & 15;
            Wsm[c][co][khw] = w[((size_t)co * 128 + c0 + c) * 16 + khw];
        }
        __syncthreads();
#pragma unroll
        for (int c = 0; c < 8; ++c) {
#pragma unroll
            for (int dh = 0; dh < 2; ++dh) {
#pragma unroll
                for (int dw = 0; dw < 2; ++dw) {
                    float a = P[c][ihl0 + dh][iwl0 + dw];
                    int khw = ((ph + (dh << 1)) << 2) + pw + (dw << 1);
                    acc0 += a * Wsm[c][0][khw];
                    acc1 += a * Wsm[c][1][khw];
                    acc2 += a * Wsm[c][2][khw];
                }
            }
        }
        __syncthreads();
    }
    const int oh = oh0 + py, ow = ow0 + px;
    size_t base = ((size_t)n * 3) * 65536 + ((size_t)oh << 8) + ow;
    out[base]          = tanhf(acc0 + bias[0]);
    out[base + 65536]  = tanhf(acc1 + bias[1]);
    out[base + 131072] = tanhf(acc2 + bias[2]);
}

// =============== group-norm stats ===============
__global__ __launch_bounds__(256) void gn_stats_kernel(const float* __restrict__ x, int span)
{
    const float* p = x + (size_t)blockIdx.x * span;
    float s = 0.f, ss = 0.f;
    for (int i = threadIdx.x; i < span; i += 256) {
        float v = p[i];
        s += v; ss += v * v;
    }
#pragma unroll
    for (int o = 16; o; o >>= 1) {
        s  += __shfl_down_sync(0xffffffffu, s, o);
        ss += __shfl_down_sync(0xffffffffu, ss, o);
    }
    __shared__ float as[8], bs[8];
    int wi = threadIdx.x >> 5, l = threadIdx.x & 31;
    if (l == 0) { as[wi] = s; bs[wi] = ss; }
    __syncthreads();
    if (threadIdx.x == 0) {
        s = 0.f; ss = 0.f;
#pragma unroll
        for (int i = 0; i < 8; ++i) { s += as[i]; ss += bs[i]; }
        float m = s / (float)span;
        float var = ss / (float)span - m * m;
        g_mean[blockIdx.x] = m;
        g_rstd[blockIdx.x] = rsqrtf(var + 1e-5f);
    }
}

// =============== fused GN apply + SiLU ===============
__global__ __launch_bounds__(256) void gn_apply_silu_kernel(
    float* __restrict__ x, const float* __restrict__ gamma, const float* __restrict__ beta,
    int C, int HW, int cpg)
{
    size_t i = (size_t)blockIdx.x * 256 + threadIdx.x;
    size_t e = i * 4;
    size_t ch = e / (size_t)HW;
    int c = (int)(ch % C);
    int n = (int)(ch / C);
    int gi = n * 32 + c / cpg;
    float m = g_mean[gi], r = g_rstd[gi];
    float ga = gamma[c], be = beta[c];
    float4 v = *reinterpret_cast<float4*>(x + e);
    float y;
    y = (v.x - m) * r * ga + be; v.x = y / (1.f + expf(-y));
    y = (v.y - m) * r * ga + be; v.y = y / (1.f + expf(-y));
    y = (v.z - m) * r * ga + be; v.z = y / (1.f + expf(-y));
    y = (v.w - m) * r * ga + be; v.w = y / (1.f + expf(-y));
    *reinterpret_cast<float4*>(x + e) = v;
}

// =============== 1x1 conv 512->32 ===============
__global__ __launch_bounds__(256) void conv1x1_enc3_kernel(
    const float* __restrict__ in, const float* __restrict__ w,
    const float* __restrict__ bias, float* __restrict__ out)
{
    const int t = blockIdx.x * 256 + threadIdx.x;
    const int n = t >> 10, pix = t & 1023;
    __shared__ float wsm[128][33];
    float acc[32];
#pragma unroll
    for (int k = 0; k < 32; ++k) acc[k] = 0.f;
    for (int c0 = 0; c0 < 512; c0 += 128) {
        __syncthreads();
        for (int idx = threadIdx.x; idx < 4096; idx += 256) {
            int co = idx >> 7, cc = idx & 127;
            wsm[cc][co] = w[(size_t)co * 512 + c0 + cc];
        }
        __syncthreads();
        for (int cc = 0; cc < 128; ++cc) {
            float a = in[(((size_t)n * 512 + c0 + cc) << 10) + pix];
#pragma unroll
            for (int k = 0; k < 32; ++k) acc[k] += a * wsm[cc][k];
        }
    }
#pragma unroll
    for (int k = 0; k < 32; ++k)
        out[(((size_t)n * 32 + k) << 10) + pix] = acc[k] + bias[k];
}

// =============== vector quantization ===============
__global__ __launch_bounds__(256) void vq_kernel(
    const float* __restrict__ z, const float* __restrict__ cbk,
    float* __restrict__ q, float* __restrict__ outq, float* __restrict__ outidx)
{
    const int m = blockIdx.x * 256 + threadIdx.x;
    float v[32];
#pragma unroll
    for (int j = 0; j < 32; ++j) v[j] = z[(size_t)m * 32 + j];
    __shared__ float csm[128][33];
    __shared__ float c2sm[128];
    float best = 3.4e38f;
    int bi = 0;
    for (int k0 = 0; k0 < 1024; k0 += 128) {
        __syncthreads();
        for (int idx = threadIdx.x; idx < 4096; idx += 256)
            csm[idx >> 5][idx & 31] = cbk[(size_t)k0 * 32 + idx];
        __syncthreads();
        if (threadIdx.x < 128) {
            float s = 0.f;
#pragma unroll
            for (int j = 0; j < 32; ++j) { float c = csm[threadIdx.x][j]; s += c * c; }
            c2sm[threadIdx.x] = s;
        }
        __syncthreads();
        for (int k = 0; k < 128; ++k) {
            float dot = 0.f;
#pragma unroll
            for (int j = 0; j < 32; ++j) dot += v[j] * csm[k][j];
            float d = c2sm[k] - 2.f * dot;
            if (d < best) { best = d; bi = k0 + k; }
        }
    }
#pragma unroll
    for (int j = 0; j < 32; ++j) {
        float qv = cbk[(size_t)bi * 32 + j];
        q[(size_t)m * 32 + j] = qv;
        outq[(size_t)m * 32 + j] = qv;
    }
    outidx[m] = (float)bi;
}

// =============== 1x1 conv 32->512 ===============
__global__ __launch_bounds__(256) void conv1x1_dec0_kernel(
    const float* __restrict__ q, const float* __restrict__ w,
    const float* __restrict__ bias, float* __restrict__ out)
{
    const int n = blockIdx.x >> 4;
    const int pix0 = (blockIdx.x & 15) << 6;
    const int cob = blockIdx.y << 6;
    __shared__ float qsm[32][64];
    __shared__ float wsm[32][65];
    const int tid = threadIdx.x;
    const int p = tid & 63, cg = tid >> 6;
    for (int idx = tid; idx < 2048; idx += 256) {
        int ci = idx >> 6, pp = idx & 63;
        qsm[ci][pp] = q[(((size_t)n * 32 + ci) << 10) + pix0 + pp];
    }
    for (int idx = tid; idx < 2048; idx += 256) {
        int co = idx >> 5, ci = idx & 31;
        wsm[ci][co] = w[((size_t)(cob + co) << 5) + ci];
    }
    __syncthreads();
    float acc[16];
#pragma unroll
    for (int k = 0; k < 16; ++k) acc[k] = 0.f;
#pragma unroll
    for (int ci = 0; ci < 32; ++ci) {
        float a = qsm[ci][p];
#pragma unroll
        for (int k = 0; k < 16; ++k)
            acc[k] += a * wsm[ci][(cg << 4) + k];
    }
#pragma unroll
    for (int k = 0; k < 16; ++k) {
        int co = cob + (cg << 4) + k;
        out[(((size_t)n * 512 + co) << 10) + pix0 + p] = acc[k] + bias[co];
    }
}

// =================================================================================
extern "C" void kernel_launch(void* const* d_in, const int* in_sizes, int n_in,
                              void* d_out, int out_size)
{
    const float* x       = (const float*)d_in[0];
    const float* enc0_w  = (const float*)d_in[1];
    const float* enc0_b  = (const float*)d_in[2];
    const float* enc0_g  = (const float*)d_in[3];
    const float* enc0_bt = (const float*)d_in[4];
    const float* enc1_w  = (const float*)d_in[5];
    const float* enc1_b  = (const float*)d_in[6];
    const float* enc1_g  = (const float*)d_in[7];
    const float* enc1_bt = (const float*)d_in[8];
    const float* enc2_w  = (const float*)d_in[9];
    const float* enc2_b  = (const float*)d_in[10];
    const float* enc2_g  = (const float*)d_in[11];
    const float* enc2_bt = (const float*)d_in[12];
    const float* enc3_w  = (const float*)d_in[13];
    const float* enc3_b  = (const float*)d_in[14];
    const float* codebook= (const float*)d_in[15];
    const float* dec0_w  = (const float*)d_in[16];
    const float* dec0_b  = (const float*)d_in[17];
    const float* dec1_w  = (const float*)d_in[18];
    const float* dec1_b  = (const float*)d_in[19];
    const float* dec1_g  = (const float*)d_in[20];
    const float* dec1_bt = (const float*)d_in[21];
    const float* dec2_w  = (const float*)d_in[22];
    const float* dec2_b  = (const float*)d_in[23];
    const float* dec2_g  = (const float*)d_in[24];
    const float* dec2_bt = (const float*)d_in[25];
    const float* dec3_w  = (const float*)d_in[26];
    const float* dec3_b  = (const float*)d_in[27];

    float* out = (float*)d_out;

    float *bufA, *bufB, *bufC, *bufZ, *bufQ;
    cudaGetSymbolAddress((void**)&bufA, g_bufA);
    cudaGetSymbolAddress((void**)&bufB, g_bufB);
    cudaGetSymbolAddress((void**)&bufC, g_bufC);
    cudaGetSymbolAddress((void**)&bufZ, g_bufZ);
    cudaGetSymbolAddress((void**)&bufQ, g_bufQ);

    // ---- encoder ----
    conv_s2_big<<<dim3(128, 1, 16), 256>>>(x, enc0_w, enc0_b, bufA, 3, 128, 256, 256);
    gn_stats_kernel<<<512, 256>>>(bufA, 4 * 128 * 128);
    gn_apply_silu_kernel<<<32768, 256>>>(bufA, enc0_g, enc0_bt, 128, 128 * 128, 4);

    conv_s2_big<<<dim3(32, 2, 16), 256>>>(bufA, enc1_w, enc1_b, bufB, 128, 256, 128, 128);
    gn_stats_kernel<<<512, 256>>>(bufB, 8 * 64 * 64);
    gn_apply_silu_kernel<<<16384, 256>>>(bufB, enc1_g, enc1_bt, 256, 64 * 64, 8);

    conv_s2_big<<<dim3(8, 4, 16), 256>>>(bufB, enc2_w, enc2_b, bufC, 256, 512, 64, 64);
    gn_stats_kernel<<<512, 256>>>(bufC, 16 * 32 * 32);
    gn_apply_silu_kernel<<<8192, 256>>>(bufC, enc2_g, enc2_bt, 512, 32 * 32, 16);

    conv1x1_enc3_kernel<<<64, 256>>>(bufC, enc3_w, enc3_b, bufZ);

    // ---- VQ ----
    vq_kernel<<<64, 256>>>(bufZ, codebook, bufQ, out + 3145728, out + 3670016);

    // ---- decoder ----
    conv1x1_dec0_kernel<<<dim3(256, 8), 256>>>(bufQ, dec0_w, dec0_b, bufC);

    convt_big<<<dim3(32, 2, 16), 256>>>(bufC, dec1_w, dec1_b, bufB, 512, 256, 32, 32);
    gn_stats_kernel<<<512, 256>>>(bufB, 8 * 64 * 64);
    gn_apply_silu_kernel<<<16384, 256>>>(bufB, dec1_g, dec1_bt, 256, 64 * 64, 8);

    convt_big<<<dim3(128, 1, 16), 256>>>(bufB, dec2_w, dec2_b, bufA, 256, 128, 64, 64);
    gn_stats_kernel<<<512, 256>>>(bufA, 4 * 128 * 128);
    gn_apply_silu_kernel<<<32768, 256>>>(bufA, dec2_g, dec2_bt, 128, 128 * 128, 4);

    convt_final_kernel<<<dim3(256, 16), 256>>>(bufA, dec3_w, dec3_b, out);
}

// round 13
// speedup vs baseline: 1.6633x; 1.3591x over previous
#include <cuda_runtime.h>
#include <cuda_bf16.h>
#include <stdint.h>
#include <math.h>

// ---------------- scratch (device globals) ----------------
__device__ float g_bufA[33554432];  // 16x128x128x128
__device__ float g_bufB[16777216];  // 16x256x64x64
__device__ float g_bufC[8388608];   // 16x512x32x32
__device__ float g_bufZ[524288];    // 16x32x32x32
__device__ float g_bufQ[524288];
__device__ float g_mean[512];
__device__ float g_rstd[512];
// pre-split, pre-swizzled weight tiles (max: dec1 = 16*8*2*8192 = 2M bf16 per split)
__device__ __nv_bfloat16 g_wA0[2097152];
__device__ __nv_bfloat16 g_wA1[2097152];

#define SWZ128(o) ((o) ^ (((o) >> 3) & 0x70))

__device__ __forceinline__ uint32_t smem_u32(const void* p) {
    uint32_t a;
    asm("{ .reg .u64 t; cvta.to.shared.u64 t, %1; cvt.u32.u64 %0, t; }" : "=r"(a) : "l"(p));
    return a;
}
__device__ __forceinline__ void ldsm4(uint32_t* r, uint32_t addr) {
    asm volatile("ldmatrix.sync.aligned.m8n8.x4.shared.b16 {%0,%1,%2,%3}, [%4];"
        : "=r"(r[0]), "=r"(r[1]), "=r"(r[2]), "=r"(r[3]) : "r"(addr));
}
__device__ __forceinline__ void mma16816(float* c, const uint32_t* a, uint32_t b0, uint32_t b1) {
    asm volatile("mma.sync.aligned.m16n8k16.row.col.f32.bf16.bf16.f32 "
        "{%0,%1,%2,%3}, {%4,%5,%6,%7}, {%8,%9}, {%0,%1,%2,%3};"
        : "+f"(c[0]), "+f"(c[1]), "+f"(c[2]), "+f"(c[3])
        : "r"(a[0]), "r"(a[1]), "r"(a[2]), "r"(a[3]), "r"(b0), "r"(b1));
}

// ======= weight transform: fp32 [Cout][Cin][16] -> split bf16 swizzled tiles =======
// tile t = (khw*nCh + ch)*nCoB + cob ; tile = [128 co][64 kk] bf16, 128B rows, SW128
__global__ __launch_bounds__(256) void wsplit_kernel(const float* __restrict__ w, int Cin, int nCh, int nCoB)
{
    int e = blockIdx.x * 256 + threadIdx.x;
    int t = e >> 13;
    int r = e & 8191;
    int co = r >> 6, kk = r & 63;
    int cob = t % nCoB;
    int rest = t / nCoB;
    int ch = rest % nCh;
    int tap = rest / nCh;
    float v = w[((size_t)(cob * 128 + co) * Cin + ch * 64 + kk) * 16 + tap];
    __nv_bfloat16 h0 = __float2bfloat16(v);
    __nv_bfloat16 h1 = __float2bfloat16(v - __bfloat162float(h0));
    uint32_t sw = SWZ128((uint32_t)(co * 128 + kk * 2)) >> 1;
    g_wA0[(size_t)t * 8192 + sw] = h0;
    g_wA1[(size_t)t * 8192 + sw] = h1;
}

// ======= HMMA transposed conv k4 s2 p1: per parity class, D[128co x 64px] per CTA =======
// GEMM: M=Cout, N=class-pixels, K=Cin*4 taps. bf16 3-pass split (a0b0+a0b1+a1b0).
// smem: A0 @0 (16K), A1 @16384, B0 @32768 (8K), B1 @40960.  Total 48K dynamic.
__global__ __launch_bounds__(256) void convt_mma(
    const float* __restrict__ in, const float* __restrict__ bias, float* __restrict__ out,
    int Cin, int Cout, int Hin, int Wlog, int nCh, int nCoB)
{
    extern __shared__ __align__(128) char smem[];
    const uint32_t sb = smem_u32(smem);
    const int tid = threadIdx.x;
    const int lane = tid & 31, wid = tid >> 5;
    const int wco = wid & 3, wpx = wid >> 2;
    const int Win = 1 << Wlog;
    const int Wout = Win << 1;
    const int n = blockIdx.z >> 2;
    const int cls = blockIdx.z & 3;
    const int ph = cls >> 1, pw = cls & 1;
    const int px0 = blockIdx.x * 64;
    const int cob = blockIdx.y;

    float acc[2][4][4];
#pragma unroll
    for (int a = 0; a < 2; ++a)
#pragma unroll
        for (int b = 0; b < 4; ++b)
#pragma unroll
            for (int c = 0; c < 4; ++c) acc[a][b][c] = 0.f;

    const size_t HW = (size_t)Hin << Wlog;
    const float* inb = in + (size_t)n * Cin * HW;

    // B staging coords: p = tid&63 (px), 16 kk values per thread
    const int p = tid & 63;
    const int pxs = px0 + p;
    const int th = pxs >> Wlog, tw = pxs & (Win - 1);

    // ldmatrix per-lane row byte offsets
    const int rA0 = (wco * 32 + (lane & 15)) * 128;
    const int rA1 = rA0 + 2048;
    const int aC  = (lane >> 4) * 16;
    const int rB0 = (wpx * 32 + (lane & 7) + ((lane >> 4) << 3)) * 128;
    const int rB1 = rB0 + 2048;
    const int bC  = ((lane >> 3) & 1) * 16;

    for (int d = 0; d < 4; ++d) {
        const int dh = d >> 1, dw = d & 1;
        const int ih = th + ph + dh - 1, iw = tw + pw + dw - 1;
        const bool ok = (unsigned)ih < (unsigned)Hin && (unsigned)iw < (unsigned)Win;
        const float* cb = inb + (size_t)ih * Win + iw;
        const int khw = (ph + 2 * dh) * 4 + (pw + 2 * dw);
        for (int ch = 0; ch < nCh; ++ch) {
            __syncthreads();   // previous tile fully consumed
            // stage A: copy pre-split swizzled weight tiles
            {
                size_t tb = ((size_t)(khw * nCh + ch) * nCoB + cob) * 8192;
                const uint4* s0 = (const uint4*)(g_wA0 + tb);
                const uint4* s1 = (const uint4*)(g_wA1 + tb);
                uint4* d0 = (uint4*)(smem);
                uint4* d1 = (uint4*)(smem + 16384);
                for (int i = tid; i < 1024; i += 256) { d0[i] = s0[i]; d1[i] = s1[i]; }
            }
            // stage B: im2col gather, split bf16, K-major swizzled
            {
                char* b0c = smem + 32768;
                char* b1c = smem + 40960;
                const float* cc = cb + (size_t)(ch * 64) * HW;
#pragma unroll
                for (int i = 0; i < 16; ++i) {
                    int kk = (tid >> 6) + i * 4;
                    float v = ok ? cc[(size_t)kk * HW] : 0.f;
                    __nv_bfloat16 h0 = __float2bfloat16(v);
                    __nv_bfloat16 h1 = __float2bfloat16(v - __bfloat162float(h0));
                    uint32_t off = SWZ128((uint32_t)(p * 128 + kk * 2));
                    *(__nv_bfloat16*)(b0c + off) = h0;
                    *(__nv_bfloat16*)(b1c + off) = h1;
                }
            }
            __syncthreads();
            // compute: 3 split passes x 4 k-steps
#pragma unroll 1
            for (int pass = 0; pass < 3; ++pass) {
                const uint32_t Ab = sb + ((pass == 2) ? 16384u : 0u);
                const uint32_t Bb = sb + ((pass == 1) ? 40960u : 32768u);
#pragma unroll
                for (int ks = 0; ks < 4; ++ks) {
                    const int kb = ks * 32;
                    uint32_t af0[4], af1[4], bf0[4], bf1[4];
                    ldsm4(af0, Ab + SWZ128((uint32_t)(rA0 + kb + aC)));
                    ldsm4(af1, Ab + SWZ128((uint32_t)(rA1 + kb + aC)));
                    ldsm4(bf0, Bb + SWZ128((uint32_t)(rB0 + kb + bC)));
                    ldsm4(bf1, Bb + SWZ128((uint32_t)(rB1 + kb + bC)));
                    mma16816(acc[0][0], af0, bf0[0], bf0[1]);
                    mma16816(acc[0][1], af0, bf0[2], bf0[3]);
                    mma16816(acc[0][2], af0, bf1[0], bf1[1]);
                    mma16816(acc[0][3], af0, bf1[2], bf1[3]);
                    mma16816(acc[1][0], af1, bf0[0], bf0[1]);
                    mma16816(acc[1][1], af1, bf0[2], bf0[3]);
                    mma16816(acc[1][2], af1, bf1[0], bf1[1]);
                    mma16816(acc[1][3], af1, bf1[2], bf1[3]);
                }
            }
        }
    }
    // epilogue: c-frag (m16n8): c0=(qr,qc) c1=(qr,qc+1) c2=(qr+8,qc) c3=(qr+8,qc+1)
    const int qr = lane >> 2, qc = (lane & 3) * 2;
    const size_t HWo = (size_t)(Hin << 1) * Wout;
#pragma unroll
    for (int mt = 0; mt < 2; ++mt) {
#pragma unroll
        for (int half = 0; half < 2; ++half) {
            int co = cob * 128 + wco * 32 + mt * 16 + qr + half * 8;
            float b = bias[co];
            float* ob = out + ((size_t)n * Cout + co) * HWo;
#pragma unroll
            for (int nt = 0; nt < 4; ++nt) {
                int pxl = px0 + wpx * 32 + nt * 8 + qc;
                int th2 = pxl >> Wlog, tw2 = pxl & (Win - 1);
                size_t o = (size_t)(2 * th2 + ph) * Wout + 2 * tw2 + pw;
                ob[o]     = acc[mt][nt][half * 2 + 0] + b;
                ob[o + 2] = acc[mt][nt][half * 2 + 1] + b;
            }
        }
    }
}

// packed f32x2 FMA
__device__ __forceinline__ void ffma2(float2& acc, float2 a, float2 b) {
    unsigned long long ua = *reinterpret_cast<unsigned long long*>(&a);
    unsigned long long ub = *reinterpret_cast<unsigned long long*>(&b);
    unsigned long long uc = *reinterpret_cast<unsigned long long*>(&acc);
    asm("fma.rn.f32x2 %0, %1, %2, %0;" : "+l"(uc) : "l"(ua), "l"(ub));
    acc = *reinterpret_cast<float2*>(&uc);
}

// =============== SIMT stride-2 conv (encoder) ===============
__global__ __launch_bounds__(256, 2) void conv_s2_big(
    const float* __restrict__ in, const float* __restrict__ w,
    const float* __restrict__ bias, float* __restrict__ out,
    int Cin, int Cout, int Hin, int Win)
{
    const int Hout = Hin >> 1, Wout = Win >> 1;
    const int tilesX = Wout >> 4;
    const int oh0 = (blockIdx.x / tilesX) << 3;
    const int ow0 = (blockIdx.x % tilesX) << 4;
    const int cob = blockIdx.y << 7;
    const int n = blockIdx.z;

    __shared__ __align__(8)  float P[4][18][36];
    __shared__ __align__(16) float Wt[4][16][132];

    const int tid = threadIdx.x;
    const int colx = tid & 15;
    const int cog  = tid >> 4;

    float2 acc[8][4];
#pragma unroll
    for (int r = 0; r < 8; ++r)
#pragma unroll
        for (int k = 0; k < 4; ++k) acc[r][k] = make_float2(0.f, 0.f);

    const float* inb = in + (size_t)n * Cin * Hin * Win;

    for (int c0 = 0; c0 < Cin; c0 += 4) {
        for (int idx = tid; idx < 8192; idx += 256) {
            int khw = idx & 15, r = idx >> 4;
            int co = r & 127, c = r >> 7;
            float v = 0.f;
            if (c0 + c < Cin)
                v = w[((size_t)(cob + co) * Cin + c0 + c) * 16 + khw];
            Wt[c][khw][co] = v;
        }
        for (int idx = tid; idx < 2448; idx += 256) {
            int c = idx / 612, r = idx - c * 612;
            int pr = r / 34, pc = r - pr * 34;
            int ih = 2 * oh0 - 1 + pr, iw = 2 * ow0 - 1 + pc;
            float v = 0.f;
            if (c0 + c < Cin && (unsigned)ih < (unsigned)Hin && (unsigned)iw < (unsigned)Win)
                v = inb[((size_t)(c0 + c) * Hin + ih) * Win + iw];
            P[c][pr][pc] = v;
        }
        __syncthreads();

#pragma unroll 1
        for (int c = 0; c < 4; ++c) {
#pragma unroll
            for (int kh = 0; kh < 4; ++kh) {
#pragma unroll
                for (int kwp = 0; kwp < 2; ++kwp) {
                    float2 av[8];
#pragma unroll
                    for (int r = 0; r < 8; ++r)
                        av[r] = *reinterpret_cast<const float2*>(&P[c][2 * r + kh][2 * colx + 2 * kwp]);
                    const int khw0 = (kh << 2) + 2 * kwp;
                    const float4* w0 = reinterpret_cast<const float4*>(&Wt[c][khw0][cog << 3]);
                    const float4* w1 = reinterpret_cast<const float4*>(&Wt[c][khw0 + 1][cog << 3]);
                    float4 wA0 = w0[0], wB0 = w0[1];
                    float4 wA1 = w1[0], wB1 = w1[1];
                    float2 p00 = make_float2(wA0.x, wA0.y), p01 = make_float2(wA0.z, wA0.w);
                    float2 p02 = make_float2(wB0.x, wB0.y), p03 = make_float2(wB0.z, wB0.w);
                    float2 p10 = make_float2(wA1.x, wA1.y), p11 = make_float2(wA1.z, wA1.w);
                    float2 p12 = make_float2(wB1.x, wB1.y), p13 = make_float2(wB1.z, wB1.w);
#pragma unroll
                    for (int r = 0; r < 8; ++r) {
                        float2 ax = make_float2(av[r].x, av[r].x);
                        float2 ay = make_float2(av[r].y, av[r].y);
                        ffma2(acc[r][0], ax, p00);
                        ffma2(acc[r][1], ax, p01);
                        ffma2(acc[r][2], ax, p02);
                        ffma2(acc[r][3], ax, p03);
                        ffma2(acc[r][0], ay, p10);
                        ffma2(acc[r][1], ay, p11);
                        ffma2(acc[r][2], ay, p12);
                        ffma2(acc[r][3], ay, p13);
                    }
                }
            }
        }
        __syncthreads();
    }

#pragma unroll
    for (int kp = 0; kp < 4; ++kp) {
        int co = cob + (cog << 3) + (kp << 1);
        float b0 = bias[co], b1 = bias[co + 1];
        float* o0 = out + (((size_t)n * Cout + co) * Hout + oh0) * Wout + ow0 + colx;
        float* o1 = o0 + (size_t)Hout * Wout;
#pragma unroll
        for (int r = 0; r < 8; ++r) {
            o0[(size_t)r * Wout] = acc[r][kp].x + b0;
            o1[(size_t)r * Wout] = acc[r][kp].y + b1;
        }
    }
}

// =============== final transposed conv 128->3 + tanh ===============
__global__ __launch_bounds__(256) void convt_final_kernel(
    const float* __restrict__ in, const float* __restrict__ w,
    const float* __restrict__ bias, float* __restrict__ out)
{
    const int n = blockIdx.y;
    const int oh0 = (blockIdx.x >> 4) << 4;
    const int ow0 = (blockIdx.x & 15) << 4;
    __shared__ float P[8][10][11];
    __shared__ float Wsm[8][3][17];
    const int tid = threadIdx.x;
    const int py = tid >> 4, px = tid & 15;
    const int ph = py & 1, pw = px & 1;
    const int ihl0 = (py + ph) >> 1, iwl0 = (px + pw) >> 1;
    const int r0 = (oh0 >> 1) - 1, col0 = (ow0 >> 1) - 1;
    float acc0 = 0.f, acc1 = 0.f, acc2 = 0.f;
    const float* inb = in + ((size_t)n << 21);

    for (int c0 = 0; c0 < 128; c0 += 8) {
        for (int idx = tid; idx < 800; idx += 256) {
            int c = idx / 100, r = idx - c * 100;
            int rr = r / 10, cc = r - rr * 10;
            int ih = r0 + rr, iw = col0 + cc;
            float v = 0.f;
            if ((unsigned)ih < 128u && (unsigned)iw < 128u)
                v = inb[((size_t)(c0 + c) << 14) + (ih << 7) + iw];
            P[c][rr][cc] = v;
        }
        for (int idx = tid; idx < 384; idx += 256) {
            int c = idx / 48, r = idx - c * 48;
            int co = r >> 4, khw = r & 15;
            Wsm[c][co][khw] = w[((size_t)co * 128 + c0 + c) * 16 + khw];
        }
        __syncthreads();
#pragma unroll
        for (int c = 0; c < 8; ++c) {
#pragma unroll
            for (int dh = 0; dh < 2; ++dh) {
#pragma unroll
                for (int dw = 0; dw < 2; ++dw) {
                    float a = P[c][ihl0 + dh][iwl0 + dw];
                    int khw = ((ph + (dh << 1)) << 2) + pw + (dw << 1);
                    acc0 += a * Wsm[c][0][khw];
                    acc1 += a * Wsm[c][1][khw];
                    acc2 += a * Wsm[c][2][khw];
                }
            }
        }
        __syncthreads();
    }
    const int oh = oh0 + py, ow = ow0 + px;
    size_t base = ((size_t)n * 3) * 65536 + ((size_t)oh << 8) + ow;
    out[base]          = tanhf(acc0 + bias[0]);
    out[base + 65536]  = tanhf(acc1 + bias[1]);
    out[base + 131072] = tanhf(acc2 + bias[2]);
}

// =============== group-norm stats ===============
__global__ __launch_bounds__(256) void gn_stats_kernel(const float* __restrict__ x, int span)
{
    const float* p = x + (size_t)blockIdx.x * span;
    float s = 0.f, ss = 0.f;
    for (int i = threadIdx.x; i < span; i += 256) {
        float v = p[i];
        s += v; ss += v * v;
    }
#pragma unroll
    for (int o = 16; o; o >>= 1) {
        s  += __shfl_down_sync(0xffffffffu, s, o);
        ss += __shfl_down_sync(0xffffffffu, ss, o);
    }
    __shared__ float as[8], bs[8];
    int wi = threadIdx.x >> 5, l = threadIdx.x & 31;
    if (l == 0) { as[wi] = s; bs[wi] = ss; }
    __syncthreads();
    if (threadIdx.x == 0) {
        s = 0.f; ss = 0.f;
#pragma unroll
        for (int i = 0; i < 8; ++i) { s += as[i]; ss += bs[i]; }
        float m = s / (float)span;
        float var = ss / (float)span - m * m;
        g_mean[blockIdx.x] = m;
        g_rstd[blockIdx.x] = rsqrtf(var + 1e-5f);
    }
}

// =============== fused GN apply + SiLU ===============
__global__ __launch_bounds__(256) void gn_apply_silu_kernel(
    float* __restrict__ x, const float* __restrict__ gamma, const float* __restrict__ beta,
    int C, int HW, int cpg)
{
    size_t i = (size_t)blockIdx.x * 256 + threadIdx.x;
    size_t e = i * 4;
    size_t ch = e / (size_t)HW;
    int c = (int)(ch % C);
    int n = (int)(ch / C);
    int gi = n * 32 + c / cpg;
    float m = g_mean[gi], r = g_rstd[gi];
    float ga = gamma[c], be = beta[c];
    float4 v = *reinterpret_cast<float4*>(x + e);
    float y;
    y = (v.x - m) * r * ga + be; v.x = y / (1.f + expf(-y));
    y = (v.y - m) * r * ga + be; v.y = y / (1.f + expf(-y));
    y = (v.z - m) * r * ga + be; v.z = y / (1.f + expf(-y));
    y = (v.w - m) * r * ga + be; v.w = y / (1.f + expf(-y));
    *reinterpret_cast<float4*>(x + e) = v;
}

// =============== 1x1 conv 512->32 ===============
__global__ __launch_bounds__(256) void conv1x1_enc3_kernel(
    const float* __restrict__ in, const float* __restrict__ w,
    const float* __restrict__ bias, float* __restrict__ out)
{
    const int t = blockIdx.x * 256 + threadIdx.x;
    const int n = t >> 10, pix = t & 1023;
    __shared__ float wsm[128][33];
    float acc[32];
#pragma unroll
    for (int k = 0; k < 32; ++k) acc[k] = 0.f;
    for (int c0 = 0; c0 < 512; c0 += 128) {
        __syncthreads();
        for (int idx = threadIdx.x; idx < 4096; idx += 256) {
            int co = idx >> 7, cc = idx & 127;
            wsm[cc][co] = w[(size_t)co * 512 + c0 + cc];
        }
        __syncthreads();
        for (int cc = 0; cc < 128; ++cc) {
            float a = in[(((size_t)n * 512 + c0 + cc) << 10) + pix];
#pragma unroll
            for (int k = 0; k < 32; ++k) acc[k] += a * wsm[cc][k];
        }
    }
#pragma unroll
    for (int k = 0; k < 32; ++k)
        out[(((size_t)n * 32 + k) << 10) + pix] = acc[k] + bias[k];
}

// =============== vector quantization ===============
__global__ __launch_bounds__(256) void vq_kernel(
    const float* __restrict__ z, const float* __restrict__ cbk,
    float* __restrict__ q, float* __restrict__ outq, float* __restrict__ outidx)
{
    const int m = blockIdx.x * 256 + threadIdx.x;
    float v[32];
#pragma unroll
    for (int j = 0; j < 32; ++j) v[j] = z[(size_t)m * 32 + j];
    __shared__ float csm[128][33];
    __shared__ float c2sm[128];
    float best = 3.4e38f;
    int bi = 0;
    for (int k0 = 0; k0 < 1024; k0 += 128) {
        __syncthreads();
        for (int idx = threadIdx.x; idx < 4096; idx += 256)
            csm[idx >> 5][idx & 31] = cbk[(size_t)k0 * 32 + idx];
        __syncthreads();
        if (threadIdx.x < 128) {
            float s = 0.f;
#pragma unroll
            for (int j = 0; j < 32; ++j) { float c = csm[threadIdx.x][j]; s += c * c; }
            c2sm[threadIdx.x] = s;
        }
        __syncthreads();
        for (int k = 0; k < 128; ++k) {
            float dot = 0.f;
#pragma unroll
            for (int j = 0; j < 32; ++j) dot += v[j] * csm[k][j];
            float d = c2sm[k] - 2.f * dot;
            if (d < best) { best = d; bi = k0 + k; }
        }
    }
#pragma unroll
    for (int j = 0; j < 32; ++j) {
        float qv = cbk[(size_t)bi * 32 + j];
        q[(size_t)m * 32 + j] = qv;
        outq[(size_t)m * 32 + j] = qv;
    }
    outidx[m] = (float)bi;
}

// =============== 1x1 conv 32->512 ===============
__global__ __launch_bounds__(256) void conv1x1_dec0_kernel(
    const float* __restrict__ q, const float* __restrict__ w,
    const float* __restrict__ bias, float* __restrict__ out)
{
    const int n = blockIdx.x >> 4;
    const int pix0 = (blockIdx.x & 15) << 6;
    const int cob = blockIdx.y << 6;
    __shared__ float qsm[32][64];
    __shared__ float wsm[32][65];
    const int tid = threadIdx.x;
    const int p = tid & 63, cg = tid >> 6;
    for (int idx = tid; idx < 2048; idx += 256) {
        int ci = idx >> 6, pp = idx & 63;
        qsm[ci][pp] = q[(((size_t)n * 32 + ci) << 10) + pix0 + pp];
    }
    for (int idx = tid; idx < 2048; idx += 256) {
        int co = idx >> 5, ci = idx & 31;
        wsm[ci][co] = w[((size_t)(cob + co) << 5) + ci];
    }
    __syncthreads();
    float acc[16];
#pragma unroll
    for (int k = 0; k < 16; ++k) acc[k] = 0.f;
#pragma unroll
    for (int ci = 0; ci < 32; ++ci) {
        float a = qsm[ci][p];
#pragma unroll
        for (int k = 0; k < 16; ++k)
            acc[k] += a * wsm[ci][(cg << 4) + k];
    }
#pragma unroll
    for (int k = 0; k < 16; ++k) {
        int co = cob + (cg << 4) + k;
        out[(((size_t)n * 512 + co) << 10) + pix0 + p] = acc[k] + bias[co];
    }
}

// =================================================================================
extern "C" void kernel_launch(void* const* d_in, const int* in_sizes, int n_in,
                              void* d_out, int out_size)
{
    const float* x       = (const float*)d_in[0];
    const float* enc0_w  = (const float*)d_in[1];
    const float* enc0_b  = (const float*)d_in[2];
    const float* enc0_g  = (const float*)d_in[3];
    const float* enc0_bt = (const float*)d_in[4];
    const float* enc1_w  = (const float*)d_in[5];
    const float* enc1_b  = (const float*)d_in[6];
    const float* enc1_g  = (const float*)d_in[7];
    const float* enc1_bt = (const float*)d_in[8];
    const float* enc2_w  = (const float*)d_in[9];
    const float* enc2_b  = (const float*)d_in[10];
    const float* enc2_g  = (const float*)d_in[11];
    const float* enc2_bt = (const float*)d_in[12];
    const float* enc3_w  = (const float*)d_in[13];
    const float* enc3_b  = (const float*)d_in[14];
    const float* codebook= (const float*)d_in[15];
    const float* dec0_w  = (const float*)d_in[16];
    const float* dec0_b  = (const float*)d_in[17];
    const float* dec1_w  = (const float*)d_in[18];
    const float* dec1_b  = (const float*)d_in[19];
    const float* dec1_g  = (const float*)d_in[20];
    const float* dec1_bt = (const float*)d_in[21];
    const float* dec2_w  = (const float*)d_in[22];
    const float* dec2_b  = (const float*)d_in[23];
    const float* dec2_g  = (const float*)d_in[24];
    const float* dec2_bt = (const float*)d_in[25];
    const float* dec3_w  = (const float*)d_in[26];
    const float* dec3_b  = (const float*)d_in[27];

    float* out = (float*)d_out;

    float *bufA, *bufB, *bufC, *bufZ, *bufQ;
    cudaGetSymbolAddress((void**)&bufA, g_bufA);
    cudaGetSymbolAddress((void**)&bufB, g_bufB);
    cudaGetSymbolAddress((void**)&bufC, g_bufC);
    cudaGetSymbolAddress((void**)&bufZ, g_bufZ);
    cudaGetSymbolAddress((void**)&bufQ, g_bufQ);

    // ---- encoder (SIMT fp32 — keeps VQ argmin exact) ----
    conv_s2_big<<<dim3(128, 1, 16), 256>>>(x, enc0_w, enc0_b, bufA, 3, 128, 256, 256);
    gn_stats_kernel<<<512, 256>>>(bufA, 4 * 128 * 128);
    gn_apply_silu_kernel<<<32768, 256>>>(bufA, enc0_g, enc0_bt, 128, 128 * 128, 4);

    conv_s2_big<<<dim3(32, 2, 16), 256>>>(bufA, enc1_w, enc1_b, bufB, 128, 256, 128, 128);
    gn_stats_kernel<<<512, 256>>>(bufB, 8 * 64 * 64);
    gn_apply_silu_kernel<<<16384, 256>>>(bufB, enc1_g, enc1_bt, 256, 64 * 64, 8);

    conv_s2_big<<<dim3(8, 4, 16), 256>>>(bufB, enc2_w, enc2_b, bufC, 256, 512, 64, 64);
    gn_stats_kernel<<<512, 256>>>(bufC, 16 * 32 * 32);
    gn_apply_silu_kernel<<<8192, 256>>>(bufC, enc2_g, enc2_bt, 512, 32 * 32, 16);

    conv1x1_enc3_kernel<<<64, 256>>>(bufC, enc3_w, enc3_b, bufZ);

    // ---- VQ ----
    vq_kernel<<<64, 256>>>(bufZ, codebook, bufQ, out + 3145728, out + 3670016);

    // ---- decoder ----
    conv1x1_dec0_kernel<<<dim3(256, 8), 256>>>(bufQ, dec0_w, dec0_b, bufC);

    // dec1: HMMA implicit GEMM (Cin=512 nCh=8, Cout=256 nCoB=2, Hin=32 Wlog=5)
    wsplit_kernel<<<8192, 256>>>(dec1_w, 512, 8, 2);
    convt_mma<<<dim3(16, 2, 64), 256, 49152>>>(bufC, dec1_b, bufB, 512, 256, 32, 5, 8, 2);
    gn_stats_kernel<<<512, 256>>>(bufB, 8 * 64 * 64);
    gn_apply_silu_kernel<<<16384, 256>>>(bufB, dec1_g, dec1_bt, 256, 64 * 64, 8);

    // dec2: HMMA implicit GEMM (Cin=256 nCh=4, Cout=128 nCoB=1, Hin=64 Wlog=6)
    wsplit_kernel<<<2048, 256>>>(dec2_w, 256, 4, 1);
    convt_mma<<<dim3(64, 1, 64), 256, 49152>>>(bufB, dec2_b, bufA, 256, 128, 64, 6, 4, 1);
    gn_stats_kernel<<<512, 256>>>(bufA, 4 * 128 * 128);
    gn_apply_silu_kernel<<<32768, 256>>>(bufA, dec2_g, dec2_bt, 128, 128 * 128, 4);

    convt_final_kernel<<<dim3(256, 16), 256>>>(bufA, dec3_w, dec3_b, out);
}

// round 14
// speedup vs baseline: 1.9774x; 1.1889x over previous
#include <cuda_runtime.h>
#include <cuda_bf16.h>
#include <stdint.h>
#include <math.h>

// ---------------- scratch (device globals) ----------------
__device__ float g_bufA[33554432];  // 16x128x128x128
__device__ float g_bufB[16777216];  // 16x256x64x64
__device__ float g_bufC[8388608];   // 16x512x32x32
__device__ float g_bufZ[524288];    // 16x32x32x32
__device__ float g_bufQ[524288];
__device__ float g_mean[512];
__device__ float g_rstd[512];
// decoder bf16 split weight tiles
__device__ __nv_bfloat16 g_wA0[2097152];
__device__ __nv_bfloat16 g_wA1[2097152];
// encoder tf32 split weight tiles (bit patterns), max enc2: 16*8*4 tiles * 4096 = 2M
__device__ uint32_t g_wT0[2097152];
__device__ uint32_t g_wT1[2097152];

#define SWZ128(o) ((o) ^ (((o) >> 3) & 0x70))

__device__ __forceinline__ uint32_t smem_u32(const void* p) {
    uint32_t a;
    asm("{ .reg .u64 t; cvta.to.shared.u64 t, %1; cvt.u32.u64 %0, t; }" : "=r"(a) : "l"(p));
    return a;
}
__device__ __forceinline__ void ldsm4(uint32_t* r, uint32_t addr) {
    asm volatile("ldmatrix.sync.aligned.m8n8.x4.shared.b16 {%0,%1,%2,%3}, [%4];"
        : "=r"(r[0]), "=r"(r[1]), "=r"(r[2]), "=r"(r[3]) : "r"(addr));
}
__device__ __forceinline__ void mma16816(float* c, const uint32_t* a, uint32_t b0, uint32_t b1) {
    asm volatile("mma.sync.aligned.m16n8k16.row.col.f32.bf16.bf16.f32 "
        "{%0,%1,%2,%3}, {%4,%5,%6,%7}, {%8,%9}, {%0,%1,%2,%3};"
        : "+f"(c[0]), "+f"(c[1]), "+f"(c[2]), "+f"(c[3])
        : "r"(a[0]), "r"(a[1]), "r"(a[2]), "r"(a[3]), "r"(b0), "r"(b1));
}
__device__ __forceinline__ void mma1688_tf(float* c, const uint32_t* a, uint32_t b0, uint32_t b1) {
    asm volatile("mma.sync.aligned.m16n8k8.row.col.f32.tf32.tf32.f32 "
        "{%0,%1,%2,%3}, {%4,%5,%6,%7}, {%8,%9}, {%0,%1,%2,%3};"
        : "+f"(c[0]), "+f"(c[1]), "+f"(c[2]), "+f"(c[3])
        : "r"(a[0]), "r"(a[1]), "r"(a[2]), "r"(a[3]), "r"(b0), "r"(b1));
}
__device__ __forceinline__ uint32_t to_tf32(float v) {
    uint32_t r;
    asm("cvt.rna.tf32.f32 %0, %1;" : "=r"(r) : "f"(v));
    return r;
}

// ======= bf16 weight transform (decoder): fp32 [Cout][Cin][16] -> split tiles =======
// tile t = (khw*nCh + ch)*nCoB + cob ; tile = [128 co][64 kk] bf16 SW128
__global__ __launch_bounds__(256) void wsplit_kernel(const float* __restrict__ w, int Cin, int nCh, int nCoB)
{
    int e = blockIdx.x * 256 + threadIdx.x;
    int t = e >> 13;
    int r = e & 8191;
    int co = r >> 6, kk = r & 63;
    int cob = t % nCoB;
    int rest = t / nCoB;
    int ch = rest % nCh;
    int tap = rest / nCh;
    float v = w[((size_t)(cob * 128 + co) * Cin + ch * 64 + kk) * 16 + tap];
    __nv_bfloat16 h0 = __float2bfloat16(v);
    __nv_bfloat16 h1 = __float2bfloat16(v - __bfloat162float(h0));
    uint32_t sw = SWZ128((uint32_t)(co * 128 + kk * 2)) >> 1;
    g_wA0[(size_t)t * 8192 + sw] = h0;
    g_wA1[(size_t)t * 8192 + sw] = h1;
}

// ======= tf32 weight transform (encoder): tile = [128 co][32 kk] tf32 SW128 =======
__global__ __launch_bounds__(256) void wsplit_tf(const float* __restrict__ w, int Cin, int nCh, int nCoB)
{
    int e = blockIdx.x * 256 + threadIdx.x;
    int t = e >> 12;
    int r = e & 4095;
    int co = r >> 5, kk = r & 31;
    int cob = t % nCoB;
    int rest = t / nCoB;
    int ch = rest % nCh;
    int tap = rest / nCh;
    float v = w[((size_t)(cob * 128 + co) * Cin + ch * 32 + kk) * 16 + tap];
    uint32_t hi = to_tf32(v);
    uint32_t lo = to_tf32(v - __uint_as_float(hi));
    uint32_t sw = SWZ128((uint32_t)(co * 128 + kk * 4)) >> 2;
    g_wT0[(size_t)t * 4096 + sw] = hi;
    g_wT1[(size_t)t * 4096 + sw] = lo;
}

// ======= tf32 HMMA stride-2 conv: D[128co x 64px] per CTA, 3-pass tf32 split =======
// smem: A0 @0 (16K), A1 @16384, B0 @32768 (8K), B1 @40960.  48K dynamic.
__global__ __launch_bounds__(256) void conv_s2_tf(
    const float* __restrict__ in, const float* __restrict__ bias, float* __restrict__ out,
    int Cin, int Cout, int Hin, int Win, int WlogO, int nCh, int nCoB)
{
    extern __shared__ __align__(128) char smem[];
    const uint32_t sb = smem_u32(smem);
    const int tid = threadIdx.x;
    const int lane = tid & 31, wid = tid >> 5;
    const int wco = wid & 3, wpx = wid >> 2;
    const int WoutO = 1 << WlogO;
    const int px0 = blockIdx.x * 64;
    const int cob = blockIdx.y;
    const int n = blockIdx.z;

    float acc[2][4][4];
#pragma unroll
    for (int a = 0; a < 2; ++a)
#pragma unroll
        for (int b = 0; b < 4; ++b)
#pragma unroll
            for (int c = 0; c < 4; ++c) acc[a][b][c] = 0.f;

    const size_t HW = (size_t)Hin * Win;
    const float* inb = in + (size_t)n * Cin * HW;

    const int p = tid & 63;
    const int px = px0 + p;
    const int oh = px >> WlogO, ow = px & (WoutO - 1);

    // fragment addresses (byte offsets before swizzle)
    const int arow = wco * 32 + (lane >> 2);
    const int acol = lane & 3;
    const int brow = wpx * 32 + (lane >> 2);

    for (int tap = 0; tap < 16; ++tap) {
        const int kh = tap >> 2, kw = tap & 3;
        const int ih = 2 * oh + kh - 1, iw = 2 * ow + kw - 1;
        const bool ok = (unsigned)ih < (unsigned)Hin && (unsigned)iw < (unsigned)Win;
        const float* cb = inb + (size_t)ih * Win + iw;
        for (int ch = 0; ch < nCh; ++ch) {
            __syncthreads();
            // stage A: copy pre-split tf32 tiles (4096 u32 each)
            {
                size_t tb = ((size_t)(tap * nCh + ch) * nCoB + cob) * 4096;
                const uint4* s0 = (const uint4*)(g_wT0 + tb);
                const uint4* s1 = (const uint4*)(g_wT1 + tb);
                uint4* d0 = (uint4*)(smem);
                uint4* d1 = (uint4*)(smem + 16384);
                for (int i = tid; i < 1024; i += 256) { d0[i] = s0[i]; d1[i] = s1[i]; }
            }
            // stage B: im2col [px][32 kk] tf32 split
            {
                const float* cc = cb + (size_t)(ch * 32) * HW;
                char* b0c = smem + 32768;
                char* b1c = smem + 40960;
#pragma unroll
                for (int i = 0; i < 8; ++i) {
                    int kk = (tid >> 6) + i * 4;
                    float v = ok ? cc[(size_t)kk * HW] : 0.f;
                    uint32_t hi = to_tf32(v);
                    uint32_t lo = to_tf32(v - __uint_as_float(hi));
                    uint32_t off = SWZ128((uint32_t)(p * 128 + kk * 4));
                    *(uint32_t*)(b0c + off) = hi;
                    *(uint32_t*)(b1c + off) = lo;
                }
            }
            __syncthreads();
#pragma unroll
            for (int ks = 0; ks < 4; ++ks) {
                const int k0 = ks * 8;
                uint32_t a0f[2][4], a1f[2][4], b0f[4][2], b1f[4][2];
#pragma unroll
                for (int mt = 0; mt < 2; ++mt) {
#pragma unroll
                    for (int i = 0; i < 4; ++i) {
                        uint32_t off = SWZ128((uint32_t)((arow + mt * 16 + (i & 1) * 8) * 128 + (k0 + acol + (i >> 1) * 4) * 4));
                        a0f[mt][i] = *(const uint32_t*)(smem + off);
                        a1f[mt][i] = *(const uint32_t*)(smem + 16384 + off);
                    }
                }
#pragma unroll
                for (int nt = 0; nt < 4; ++nt) {
#pragma unroll
                    for (int j = 0; j < 2; ++j) {
                        uint32_t off = SWZ128((uint32_t)((brow + nt * 8) * 128 + (k0 + acol + j * 4) * 4));
                        b0f[nt][j] = *(const uint32_t*)(smem + 32768 + off);
                        b1f[nt][j] = *(const uint32_t*)(smem + 40960 + off);
                    }
                }
#pragma unroll
                for (int mt = 0; mt < 2; ++mt)
#pragma unroll
                    for (int nt = 0; nt < 4; ++nt) {
                        mma1688_tf(acc[mt][nt], a0f[mt], b0f[nt][0], b0f[nt][1]);
                        mma1688_tf(acc[mt][nt], a1f[mt], b0f[nt][0], b0f[nt][1]);
                        mma1688_tf(acc[mt][nt], a0f[mt], b1f[nt][0], b1f[nt][1]);
                    }
            }
        }
    }
    // epilogue
    const int qr = lane >> 2, qc = (lane & 3) * 2;
    const size_t HWo = HW >> 2;
#pragma unroll
    for (int mt = 0; mt < 2; ++mt) {
#pragma unroll
        for (int half = 0; half < 2; ++half) {
            int co = cob * 128 + wco * 32 + mt * 16 + qr + half * 8;
            float b = bias[co];
            float* ob = out + ((size_t)n * Cout + co) * HWo;
#pragma unroll
            for (int nt = 0; nt < 4; ++nt) {
                int pxl = px0 + wpx * 32 + nt * 8 + qc;
                ob[pxl]     = acc[mt][nt][half * 2 + 0] + b;
                ob[pxl + 1] = acc[mt][nt][half * 2 + 1] + b;
            }
        }
    }
}

// ======= bf16 HMMA transposed conv k4 s2 p1 (decoder) — unchanged from R13 =======
__global__ __launch_bounds__(256) void convt_mma(
    const float* __restrict__ in, const float* __restrict__ bias, float* __restrict__ out,
    int Cin, int Cout, int Hin, int Wlog, int nCh, int nCoB)
{
    extern __shared__ __align__(128) char smem[];
    const uint32_t sb = smem_u32(smem);
    const int tid = threadIdx.x;
    const int lane = tid & 31, wid = tid >> 5;
    const int wco = wid & 3, wpx = wid >> 2;
    const int Win = 1 << Wlog;
    const int Wout = Win << 1;
    const int n = blockIdx.z >> 2;
    const int cls = blockIdx.z & 3;
    const int ph = cls >> 1, pw = cls & 1;
    const int px0 = blockIdx.x * 64;
    const int cob = blockIdx.y;

    float acc[2][4][4];
#pragma unroll
    for (int a = 0; a < 2; ++a)
#pragma unroll
        for (int b = 0; b < 4; ++b)
#pragma unroll
            for (int c = 0; c < 4; ++c) acc[a][b][c] = 0.f;

    const size_t HW = (size_t)Hin << Wlog;
    const float* inb = in + (size_t)n * Cin * HW;

    const int p = tid & 63;
    const int pxs = px0 + p;
    const int th = pxs >> Wlog, tw = pxs & (Win - 1);

    const int rA0 = (wco * 32 + (lane & 15)) * 128;
    const int rA1 = rA0 + 2048;
    const int aC  = (lane >> 4) * 16;
    const int rB0 = (wpx * 32 + (lane & 7) + ((lane >> 4) << 3)) * 128;
    const int rB1 = rB0 + 2048;
    const int bC  = ((lane >> 3) & 1) * 16;

    for (int d = 0; d < 4; ++d) {
        const int dh = d >> 1, dw = d & 1;
        const int ih = th + ph + dh - 1, iw = tw + pw + dw - 1;
        const bool ok = (unsigned)ih < (unsigned)Hin && (unsigned)iw < (unsigned)Win;
        const float* cb = inb + (size_t)ih * Win + iw;
        const int khw = (ph + 2 * dh) * 4 + (pw + 2 * dw);
        for (int ch = 0; ch < nCh; ++ch) {
            __syncthreads();
            {
                size_t tb = ((size_t)(khw * nCh + ch) * nCoB + cob) * 8192;
                const uint4* s0 = (const uint4*)(g_wA0 + tb);
                const uint4* s1 = (const uint4*)(g_wA1 + tb);
                uint4* d0 = (uint4*)(smem);
                uint4* d1 = (uint4*)(smem + 16384);
                for (int i = tid; i < 1024; i += 256) { d0[i] = s0[i]; d1[i] = s1[i]; }
            }
            {
                char* b0c = smem + 32768;
                char* b1c = smem + 40960;
                const float* cc = cb + (size_t)(ch * 64) * HW;
#pragma unroll
                for (int i = 0; i < 16; ++i) {
                    int kk = (tid >> 6) + i * 4;
                    float v = ok ? cc[(size_t)kk * HW] : 0.f;
                    __nv_bfloat16 h0 = __float2bfloat16(v);
                    __nv_bfloat16 h1 = __float2bfloat16(v - __bfloat162float(h0));
                    uint32_t off = SWZ128((uint32_t)(p * 128 + kk * 2));
                    *(__nv_bfloat16*)(b0c + off) = h0;
                    *(__nv_bfloat16*)(b1c + off) = h1;
                }
            }
            __syncthreads();
#pragma unroll 1
            for (int pass = 0; pass < 3; ++pass) {
                const uint32_t Ab = sb + ((pass == 2) ? 16384u : 0u);
                const uint32_t Bb = sb + ((pass == 1) ? 40960u : 32768u);
#pragma unroll
                for (int ks = 0; ks < 4; ++ks) {
                    const int kb = ks * 32;
                    uint32_t af0[4], af1[4], bf0[4], bf1[4];
                    ldsm4(af0, Ab + SWZ128((uint32_t)(rA0 + kb + aC)));
                    ldsm4(af1, Ab + SWZ128((uint32_t)(rA1 + kb + aC)));
                    ldsm4(bf0, Bb + SWZ128((uint32_t)(rB0 + kb + bC)));
                    ldsm4(bf1, Bb + SWZ128((uint32_t)(rB1 + kb + bC)));
                    mma16816(acc[0][0], af0, bf0[0], bf0[1]);
                    mma16816(acc[0][1], af0, bf0[2], bf0[3]);
                    mma16816(acc[0][2], af0, bf1[0], bf1[1]);
                    mma16816(acc[0][3], af0, bf1[2], bf1[3]);
                    mma16816(acc[1][0], af1, bf0[0], bf0[1]);
                    mma16816(acc[1][1], af1, bf0[2], bf0[3]);
                    mma16816(acc[1][2], af1, bf1[0], bf1[1]);
                    mma16816(acc[1][3], af1, bf1[2], bf1[3]);
                }
            }
        }
    }
    const int qr = lane >> 2, qc = (lane & 3) * 2;
    const size_t HWo = (size_t)(Hin << 1) * Wout;
#pragma unroll
    for (int mt = 0; mt < 2; ++mt) {
#pragma unroll
        for (int half = 0; half < 2; ++half) {
            int co = cob * 128 + wco * 32 + mt * 16 + qr + half * 8;
            float b = bias[co];
            float* ob = out + ((size_t)n * Cout + co) * HWo;
#pragma unroll
            for (int nt = 0; nt < 4; ++nt) {
                int pxl = px0 + wpx * 32 + nt * 8 + qc;
                int th2 = pxl >> Wlog, tw2 = pxl & (Win - 1);
                size_t o = (size_t)(2 * th2 + ph) * Wout + 2 * tw2 + pw;
                ob[o]     = acc[mt][nt][half * 2 + 0] + b;
                ob[o + 2] = acc[mt][nt][half * 2 + 1] + b;
            }
        }
    }
}

// packed f32x2 FMA
__device__ __forceinline__ void ffma2(float2& acc, float2 a, float2 b) {
    unsigned long long ua = *reinterpret_cast<unsigned long long*>(&a);
    unsigned long long ub = *reinterpret_cast<unsigned long long*>(&b);
    unsigned long long uc = *reinterpret_cast<unsigned long long*>(&acc);
    asm("fma.rn.f32x2 %0, %1, %2, %0;" : "+l"(uc) : "l"(ua), "l"(ub));
    acc = *reinterpret_cast<float2*>(&uc);
}

// =============== SIMT stride-2 conv (enc0 only) ===============
__global__ __launch_bounds__(256, 2) void conv_s2_big(
    const float* __restrict__ in, const float* __restrict__ w,
    const float* __restrict__ bias, float* __restrict__ out,
    int Cin, int Cout, int Hin, int Win)
{
    const int Hout = Hin >> 1, Wout = Win >> 1;
    const int tilesX = Wout >> 4;
    const int oh0 = (blockIdx.x / tilesX) << 3;
    const int ow0 = (blockIdx.x % tilesX) << 4;
    const int cob = blockIdx.y << 7;
    const int n = blockIdx.z;

    __shared__ __align__(8)  float P[4][18][36];
    __shared__ __align__(16) float Wt[4][16][132];

    const int tid = threadIdx.x;
    const int colx = tid & 15;
    const int cog  = tid >> 4;

    float2 acc[8][4];
#pragma unroll
    for (int r = 0; r < 8; ++r)
#pragma unroll
        for (int k = 0; k < 4; ++k) acc[r][k] = make_float2(0.f, 0.f);

    const float* inb = in + (size_t)n * Cin * Hin * Win;

    for (int c0 = 0; c0 < Cin; c0 += 4) {
        for (int idx = tid; idx < 8192; idx += 256) {
            int khw = idx & 15, r = idx >> 4;
            int co = r & 127, c = r >> 7;
            float v = 0.f;
            if (c0 + c < Cin)
                v = w[((size_t)(cob + co) * Cin + c0 + c) * 16 + khw];
            Wt[c][khw][co] = v;
        }
        for (int idx = tid; idx < 2448; idx += 256) {
            int c = idx / 612, r = idx - c * 612;
            int pr = r / 34, pc = r - pr * 34;
            int ih = 2 * oh0 - 1 + pr, iw = 2 * ow0 - 1 + pc;
            float v = 0.f;
            if (c0 + c < Cin && (unsigned)ih < (unsigned)Hin && (unsigned)iw < (unsigned)Win)
                v = inb[((size_t)(c0 + c) * Hin + ih) * Win + iw];
            P[c][pr][pc] = v;
        }
        __syncthreads();

#pragma unroll 1
        for (int c = 0; c < 4; ++c) {
#pragma unroll
            for (int kh = 0; kh < 4; ++kh) {
#pragma unroll
                for (int kwp = 0; kwp < 2; ++kwp) {
                    float2 av[8];
#pragma unroll
                    for (int r = 0; r < 8; ++r)
                        av[r] = *reinterpret_cast<const float2*>(&P[c][2 * r + kh][2 * colx + 2 * kwp]);
                    const int khw0 = (kh << 2) + 2 * kwp;
                    const float4* w0 = reinterpret_cast<const float4*>(&Wt[c][khw0][cog << 3]);
                    const float4* w1 = reinterpret_cast<const float4*>(&Wt[c][khw0 + 1][cog << 3]);
                    float4 wA0 = w0[0], wB0 = w0[1];
                    float4 wA1 = w1[0], wB1 = w1[1];
                    float2 p00 = make_float2(wA0.x, wA0.y), p01 = make_float2(wA0.z, wA0.w);
                    float2 p02 = make_float2(wB0.x, wB0.y), p03 = make_float2(wB0.z, wB0.w);
                    float2 p10 = make_float2(wA1.x, wA1.y), p11 = make_float2(wA1.z, wA1.w);
                    float2 p12 = make_float2(wB1.x, wB1.y), p13 = make_float2(wB1.z, wB1.w);
#pragma unroll
                    for (int r = 0; r < 8; ++r) {
                        float2 ax = make_float2(av[r].x, av[r].x);
                        float2 ay = make_float2(av[r].y, av[r].y);
                        ffma2(acc[r][0], ax, p00);
                        ffma2(acc[r][1], ax, p01);
                        ffma2(acc[r][2], ax, p02);
                        ffma2(acc[r][3], ax, p03);
                        ffma2(acc[r][0], ay, p10);
                        ffma2(acc[r][1], ay, p11);
                        ffma2(acc[r][2], ay, p12);
                        ffma2(acc[r][3], ay, p13);
                    }
                }
            }
        }
        __syncthreads();
    }

#pragma unroll
    for (int kp = 0; kp < 4; ++kp) {
        int co = cob + (cog << 3) + (kp << 1);
        float b0 = bias[co], b1 = bias[co + 1];
        float* o0 = out + (((size_t)n * Cout + co) * Hout + oh0) * Wout + ow0 + colx;
        float* o1 = o0 + (size_t)Hout * Wout;
#pragma unroll
        for (int r = 0; r < 8; ++r) {
            o0[(size_t)r * Wout] = acc[r][kp].x + b0;
            o1[(size_t)r * Wout] = acc[r][kp].y + b1;
        }
    }
}

// =============== final transposed conv 128->3 + tanh ===============
__global__ __launch_bounds__(256) void convt_final_kernel(
    const float* __restrict__ in, const float* __restrict__ w,
    const float* __restrict__ bias, float* __restrict__ out)
{
    const int n = blockIdx.y;
    const int oh0 = (blockIdx.x >> 4) << 4;
    const int ow0 = (blockIdx.x & 15) << 4;
    __shared__ float P[8][10][11];
    __shared__ float Wsm[8][3][17];
    const int tid = threadIdx.x;
    const int py = tid >> 4, px = tid & 15;
    const int ph = py & 1, pw = px & 1;
    const int ihl0 = (py + ph) >> 1, iwl0 = (px + pw) >> 1;
    const int r0 = (oh0 >> 1) - 1, col0 = (ow0 >> 1) - 1;
    float acc0 = 0.f, acc1 = 0.f, acc2 = 0.f;
    const float* inb = in + ((size_t)n << 21);

    for (int c0 = 0; c0 < 128; c0 += 8) {
        for (int idx = tid; idx < 800; idx += 256) {
            int c = idx / 100, r = idx - c * 100;
            int rr = r / 10, cc = r - rr * 10;
            int ih = r0 + rr, iw = col0 + cc;
            float v = 0.f;
            if ((unsigned)ih < 128u && (unsigned)iw < 128u)
                v = inb[((size_t)(c0 + c) << 14) + (ih << 7) + iw];
            P[c][rr][cc] = v;
        }
        for (int idx = tid; idx < 384; idx += 256) {
            int c = idx / 48, r = idx - c * 48;
            int co = r >> 4, khw = r & 15;
            Wsm[c][co][khw] = w[((size_t)co * 128 + c0 + c) * 16 + khw];
        }
        __syncthreads();
#pragma unroll
        for (int c = 0; c < 8; ++c) {
#pragma unroll
            for (int dh = 0; dh < 2; ++dh) {
#pragma unroll
                for (int dw = 0; dw < 2; ++dw) {
                    float a = P[c][ihl0 + dh][iwl0 + dw];
                    int khw = ((ph + (dh << 1)) << 2) + pw + (dw << 1);
                    acc0 += a * Wsm[c][0][khw];
                    acc1 += a * Wsm[c][1][khw];
                    acc2 += a * Wsm[c][2][khw];
                }
            }
        }
        __syncthreads();
    }
    const int oh = oh0 + py, ow = ow0 + px;
    size_t base = ((size_t)n * 3) * 65536 + ((size_t)oh << 8) + ow;
    out[base]          = tanhf(acc0 + bias[0]);
    out[base + 65536]  = tanhf(acc1 + bias[1]);
    out[base + 131072] = tanhf(acc2 + bias[2]);
}

// =============== group-norm stats ===============
__global__ __launch_bounds__(256) void gn_stats_kernel(const float* __restrict__ x, int span)
{
    const float* p = x + (size_t)blockIdx.x * span;
    float s = 0.f, ss = 0.f;
    for (int i = threadIdx.x; i < span; i += 256) {
        float v = p[i];
        s += v; ss += v * v;
    }
#pragma unroll
    for (int o = 16; o; o >>= 1) {
        s  += __shfl_down_sync(0xffffffffu, s, o);
        ss += __shfl_down_sync(0xffffffffu, ss, o);
    }
    __shared__ float as[8], bs[8];
    int wi = threadIdx.x >> 5, l = threadIdx.x & 31;
    if (l == 0) { as[wi] = s; bs[wi] = ss; }
    __syncthreads();
    if (threadIdx.x == 0) {
        s = 0.f; ss = 0.f;
#pragma unroll
        for (int i = 0; i < 8; ++i) { s += as[i]; ss += bs[i]; }
        float m = s / (float)span;
        float var = ss / (float)span - m * m;
        g_mean[blockIdx.x] = m;
        g_rstd[blockIdx.x] = rsqrtf(var + 1e-5f);
    }
}

// =============== fused GN apply + SiLU ===============
__global__ __launch_bounds__(256) void gn_apply_silu_kernel(
    float* __restrict__ x, const float* __restrict__ gamma, const float* __restrict__ beta,
    int C, int HW, int cpg)
{
    size_t i = (size_t)blockIdx.x * 256 + threadIdx.x;
    size_t e = i * 4;
    size_t ch = e / (size_t)HW;
    int c = (int)(ch % C);
    int n = (int)(ch / C);
    int gi = n * 32 + c / cpg;
    float m = g_mean[gi], r = g_rstd[gi];
    float ga = gamma[c], be = beta[c];
    float4 v = *reinterpret_cast<float4*>(x + e);
    float y;
    y = (v.x - m) * r * ga + be; v.x = y / (1.f + expf(-y));
    y = (v.y - m) * r * ga + be; v.y = y / (1.f + expf(-y));
    y = (v.z - m) * r * ga + be; v.z = y / (1.f + expf(-y));
    y = (v.w - m) * r * ga + be; v.w = y / (1.f + expf(-y));
    *reinterpret_cast<float4*>(x + e) = v;
}

// =============== 1x1 conv 512->32 ===============
__global__ __launch_bounds__(256) void conv1x1_enc3_kernel(
    const float* __restrict__ in, const float* __restrict__ w,
    const float* __restrict__ bias, float* __restrict__ out)
{
    const int t = blockIdx.x * 256 + threadIdx.x;
    const int n = t >> 10, pix = t & 1023;
    __shared__ float wsm[128][33];
    float acc[32];
#pragma unroll
    for (int k = 0; k < 32; ++k) acc[k] = 0.f;
    for (int c0 = 0; c0 < 512; c0 += 128) {
        __syncthreads();
        for (int idx = threadIdx.x; idx < 4096; idx += 256) {
            int co = idx >> 7, cc = idx & 127;
            wsm[cc][co] = w[(size_t)co * 512 + c0 + cc];
        }
        __syncthreads();
        for (int cc = 0; cc < 128; ++cc) {
            float a = in[(((size_t)n * 512 + c0 + cc) << 10) + pix];
#pragma unroll
            for (int k = 0; k < 32; ++k) acc[k] += a * wsm[cc][k];
        }
    }
#pragma unroll
    for (int k = 0; k < 32; ++k)
        out[(((size_t)n * 32 + k) << 10) + pix] = acc[k] + bias[k];
}

// =============== vector quantization ===============
__global__ __launch_bounds__(256) void vq_kernel(
    const float* __restrict__ z, const float* __restrict__ cbk,
    float* __restrict__ q, float* __restrict__ outq, float* __restrict__ outidx)
{
    const int m = blockIdx.x * 256 + threadIdx.x;
    float v[32];
#pragma unroll
    for (int j = 0; j < 32; ++j) v[j] = z[(size_t)m * 32 + j];
    __shared__ float csm[128][33];
    __shared__ float c2sm[128];
    float best = 3.4e38f;
    int bi = 0;
    for (int k0 = 0; k0 < 1024; k0 += 128) {
        __syncthreads();
        for (int idx = threadIdx.x; idx < 4096; idx += 256)
            csm[idx >> 5][idx & 31] = cbk[(size_t)k0 * 32 + idx];
        __syncthreads();
        if (threadIdx.x < 128) {
            float s = 0.f;
#pragma unroll
            for (int j = 0; j < 32; ++j) { float c = csm[threadIdx.x][j]; s += c * c; }
            c2sm[threadIdx.x] = s;
        }
        __syncthreads();
        for (int k = 0; k < 128; ++k) {
            float dot = 0.f;
#pragma unroll
            for (int j = 0; j < 32; ++j) dot += v[j] * csm[k][j];
            float d = c2sm[k] - 2.f * dot;
            if (d < best) { best = d; bi = k0 + k; }
        }
    }
#pragma unroll
    for (int j = 0; j < 32; ++j) {
        float qv = cbk[(size_t)bi * 32 + j];
        q[(size_t)m * 32 + j] = qv;
        outq[(size_t)m * 32 + j] = qv;
    }
    outidx[m] = (float)bi;
}

// =============== 1x1 conv 32->512 ===============
__global__ __launch_bounds__(256) void conv1x1_dec0_kernel(
    const float* __restrict__ q, const float* __restrict__ w,
    const float* __restrict__ bias, float* __restrict__ out)
{
    const int n = blockIdx.x >> 4;
    const int pix0 = (blockIdx.x & 15) << 6;
    const int cob = blockIdx.y << 6;
    __shared__ float qsm[32][64];
    __shared__ float wsm[32][65];
    const int tid = threadIdx.x;
    const int p = tid & 63, cg = tid >> 6;
    for (int idx = tid; idx < 2048; idx += 256) {
        int ci = idx >> 6, pp = idx & 63;
        qsm[ci][pp] = q[(((size_t)n * 32 + ci) << 10) + pix0 + pp];
    }
    for (int idx = tid; idx < 2048; idx += 256) {
        int co = idx >> 5, ci = idx & 31;
        wsm[ci][co] = w[((size_t)(cob + co) << 5) + ci];
    }
    __syncthreads();
    float acc[16];
#pragma unroll
    for (int k = 0; k < 16; ++k) acc[k] = 0.f;
#pragma unroll
    for (int ci = 0; ci < 32; ++ci) {
        float a = qsm[ci][p];
#pragma unroll
        for (int k = 0; k < 16; ++k)
            acc[k] += a * wsm[ci][(cg << 4) + k];
    }
#pragma unroll
    for (int k = 0; k < 16; ++k) {
        int co = cob + (cg << 4) + k;
        out[(((size_t)n * 512 + co) << 10) + pix0 + p] = acc[k] + bias[co];
    }
}

// =================================================================================
extern "C" void kernel_launch(void* const* d_in, const int* in_sizes, int n_in,
                              void* d_out, int out_size)
{
    const float* x       = (const float*)d_in[0];
    const float* enc0_w  = (const float*)d_in[1];
    const float* enc0_b  = (const float*)d_in[2];
    const float* enc0_g  = (const float*)d_in[3];
    const float* enc0_bt = (const float*)d_in[4];
    const float* enc1_w  = (const float*)d_in[5];
    const float* enc1_b  = (const float*)d_in[6];
    const float* enc1_g  = (const float*)d_in[7];
    const float* enc1_bt = (const float*)d_in[8];
    const float* enc2_w  = (const float*)d_in[9];
    const float* enc2_b  = (const float*)d_in[10];
    const float* enc2_g  = (const float*)d_in[11];
    const float* enc2_bt = (const float*)d_in[12];
    const float* enc3_w  = (const float*)d_in[13];
    const float* enc3_b  = (const float*)d_in[14];
    const float* codebook= (const float*)d_in[15];
    const float* dec0_w  = (const float*)d_in[16];
    const float* dec0_b  = (const float*)d_in[17];
    const float* dec1_w  = (const float*)d_in[18];
    const float* dec1_b  = (const float*)d_in[19];
    const float* dec1_g  = (const float*)d_in[20];
    const float* dec1_bt = (const float*)d_in[21];
    const float* dec2_w  = (const float*)d_in[22];
    const float* dec2_b  = (const float*)d_in[23];
    const float* dec2_g  = (const float*)d_in[24];
    const float* dec2_bt = (const float*)d_in[25];
    const float* dec3_w  = (const float*)d_in[26];
    const float* dec3_b  = (const float*)d_in[27];

    float* out = (float*)d_out;

    float *bufA, *bufB, *bufC, *bufZ, *bufQ;
    cudaGetSymbolAddress((void**)&bufA, g_bufA);
    cudaGetSymbolAddress((void**)&bufB, g_bufB);
    cudaGetSymbolAddress((void**)&bufC, g_bufC);
    cudaGetSymbolAddress((void**)&bufZ, g_bufZ);
    cudaGetSymbolAddress((void**)&bufQ, g_bufQ);

    // ---- encoder ----
    conv_s2_big<<<dim3(128, 1, 16), 256>>>(x, enc0_w, enc0_b, bufA, 3, 128, 256, 256);
    gn_stats_kernel<<<512, 256>>>(bufA, 4 * 128 * 128);
    gn_apply_silu_kernel<<<32768, 256>>>(bufA, enc0_g, enc0_bt, 128, 128 * 128, 4);

    // enc1: tf32 HMMA (Cin=128 nCh=4, Cout=256 nCoB=2, out 64x64 -> WlogO=6)
    wsplit_tf<<<2048, 256>>>(enc1_w, 128, 4, 2);
    conv_s2_tf<<<dim3(64, 2, 16), 256, 49152>>>(bufA, enc1_b, bufB, 128, 256, 128, 128, 6, 4, 2);
    gn_stats_kernel<<<512, 256>>>(bufB, 8 * 64 * 64);
    gn_apply_silu_kernel<<<16384, 256>>>(bufB, enc1_g, enc1_bt, 256, 64 * 64, 8);

    // enc2: tf32 HMMA (Cin=256 nCh=8, Cout=512 nCoB=4, out 32x32 -> WlogO=5)
    wsplit_tf<<<8192, 256>>>(enc2_w, 256, 8, 4);
    conv_s2_tf<<<dim3(16, 4, 16), 256, 49152>>>(bufB, enc2_b, bufC, 256, 512, 64, 64, 5, 8, 4);
    gn_stats_kernel<<<512, 256>>>(bufC, 16 * 32 * 32);
    gn_apply_silu_kernel<<<8192, 256>>>(bufC, enc2_g, enc2_bt, 512, 32 * 32, 16);

    conv1x1_enc3_kernel<<<64, 256>>>(bufC, enc3_w, enc3_b, bufZ);

    // ---- VQ ----
    vq_kernel<<<64, 256>>>(bufZ, codebook, bufQ, out + 3145728, out + 3670016);

    // ---- decoder ----
    conv1x1_dec0_kernel<<<dim3(256, 8), 256>>>(bufQ, dec0_w, dec0_b, bufC);

    wsplit_kernel<<<8192, 256>>>(dec1_w, 512, 8, 2);
    convt_mma<<<dim3(16, 2, 64), 256, 49152>>>(bufC, dec1_b, bufB, 512, 256, 32, 5, 8, 2);
    gn_stats_kernel<<<512, 256>>>(bufB, 8 * 64 * 64);
    gn_apply_silu_kernel<<<16384, 256>>>(bufB, dec1_g, dec1_bt, 256, 64 * 64, 8);

    wsplit_kernel<<<2048, 256>>>(dec2_w, 256, 4, 1);
    convt_mma<<<dim3(64, 1, 64), 256, 49152>>>(bufB, dec2_b, bufA, 256, 128, 64, 6, 4, 1);
    gn_stats_kernel<<<512, 256>>>(bufA, 4 * 128 * 128);
    gn_apply_silu_kernel<<<32768, 256>>>(bufA, dec2_g, dec2_bt, 128, 128 * 128, 4);

    convt_final_kernel<<<dim3(256, 16), 256>>>(bufA, dec3_w, dec3_b, out);
}

// round 16
// speedup vs baseline: 1.9978x; 1.0103x over previous
#include <cuda_runtime.h>
#include <cuda_bf16.h>
#include <stdint.h>
#include <math.h>

// ---------------- scratch (device globals) ----------------
__device__ float g_bufA[33554432];  // 16x128x128x128
__device__ float g_bufB[16777216];  // 16x256x64x64
__device__ float g_bufC[8388608];   // 16x512x32x32
__device__ float g_bufZ[524288];    // 16x32x32x32
__device__ float g_bufQ[524288];
__device__ float g_mean[512];
__device__ float g_rstd[512];
// decoder bf16 split weight tiles
__device__ __nv_bfloat16 g_wA0[2097152];
__device__ __nv_bfloat16 g_wA1[2097152];
// encoder tf32 split weight tiles (bit patterns)
__device__ uint32_t g_wT0[2097152];
__device__ uint32_t g_wT1[2097152];

#define SWZ128(o) ((o) ^ (((o) >> 3) & 0x70))

__device__ __forceinline__ uint32_t smem_u32(const void* p) {
    uint32_t a;
    asm("{ .reg .u64 t; cvta.to.shared.u64 t, %1; cvt.u32.u64 %0, t; }" : "=r"(a) : "l"(p));
    return a;
}
__device__ __forceinline__ void ldsm4(uint32_t* r, uint32_t addr) {
    asm volatile("ldmatrix.sync.aligned.m8n8.x4.shared.b16 {%0,%1,%2,%3}, [%4];"
        : "=r"(r[0]), "=r"(r[1]), "=r"(r[2]), "=r"(r[3]) : "r"(addr));
}
__device__ __forceinline__ void mma16816(float* c, const uint32_t* a, uint32_t b0, uint32_t b1) {
    asm volatile("mma.sync.aligned.m16n8k16.row.col.f32.bf16.bf16.f32 "
        "{%0,%1,%2,%3}, {%4,%5,%6,%7}, {%8,%9}, {%0,%1,%2,%3};"
        : "+f"(c[0]), "+f"(c[1]), "+f"(c[2]), "+f"(c[3])
        : "r"(a[0]), "r"(a[1]), "r"(a[2]), "r"(a[3]), "r"(b0), "r"(b1));
}
__device__ __forceinline__ void mma1688_tf(float* c, const uint32_t* a, uint32_t b0, uint32_t b1) {
    asm volatile("mma.sync.aligned.m16n8k8.row.col.f32.tf32.tf32.f32 "
        "{%0,%1,%2,%3}, {%4,%5,%6,%7}, {%8,%9}, {%0,%1,%2,%3};"
        : "+f"(c[0]), "+f"(c[1]), "+f"(c[2]), "+f"(c[3])
        : "r"(a[0]), "r"(a[1]), "r"(a[2]), "r"(a[3]), "r"(b0), "r"(b1));
}
__device__ __forceinline__ uint32_t to_tf32(float v) {
    uint32_t r;
    asm("cvt.rna.tf32.f32 %0, %1;" : "=r"(r) : "f"(v));
    return r;
}

// ======= bf16 weight transform (decoder) =======
__global__ __launch_bounds__(256) void wsplit_kernel(const float* __restrict__ w, int Cin, int nCh, int nCoB)
{
    int e = blockIdx.x * 256 + threadIdx.x;
    int t = e >> 13;
    int r = e & 8191;
    int co = r >> 6, kk = r & 63;
    int cob = t % nCoB;
    int rest = t / nCoB;
    int ch = rest % nCh;
    int tap = rest / nCh;
    float v = w[((size_t)(cob * 128 + co) * Cin + ch * 64 + kk) * 16 + tap];
    __nv_bfloat16 h0 = __float2bfloat16(v);
    __nv_bfloat16 h1 = __float2bfloat16(v - __bfloat162float(h0));
    uint32_t sw = SWZ128((uint32_t)(co * 128 + kk * 2)) >> 1;
    g_wA0[(size_t)t * 8192 + sw] = h0;
    g_wA1[(size_t)t * 8192 + sw] = h1;
}

// ======= tf32 weight transform (encoder) =======
__global__ __launch_bounds__(256) void wsplit_tf(const float* __restrict__ w, int Cin, int nCh, int nCoB)
{
    int e = blockIdx.x * 256 + threadIdx.x;
    int t = e >> 12;
    int r = e & 4095;
    int co = r >> 5, kk = r & 31;
    int cob = t % nCoB;
    int rest = t / nCoB;
    int ch = rest % nCh;
    int tap = rest / nCh;
    float v = w[((size_t)(cob * 128 + co) * Cin + ch * 32 + kk) * 16 + tap];
    uint32_t hi = to_tf32(v);
    uint32_t lo = to_tf32(v - __uint_as_float(hi));
    uint32_t sw = SWZ128((uint32_t)(co * 128 + kk * 4)) >> 2;
    g_wT0[(size_t)t * 4096 + sw] = hi;
    g_wT1[(size_t)t * 4096 + sw] = lo;
}

// ======= tf32 HMMA stride-2 conv: D[128co x 128px] per CTA, 3-pass tf32 split =======
// smem: A0 @0 (16K), A1 @16384, B0 @32768 (16K), B1 @49152.  64K dynamic.
__global__ __launch_bounds__(256) void conv_s2_tf(
    const float* __restrict__ in, const float* __restrict__ bias, float* __restrict__ out,
    int Cin, int Cout, int Hin, int Win, int WlogO, int nCh, int nCoB)
{
    extern __shared__ __align__(128) char smem[];
    const int tid = threadIdx.x;
    const int lane = tid & 31, wid = tid >> 5;
    const int wco = wid & 3, wpx = wid >> 2;
    const int WoutO = 1 << WlogO;
    const int px0 = blockIdx.x * 128;
    const int cob = blockIdx.y;
    const int n = blockIdx.z;

    float acc[2][8][4];
#pragma unroll
    for (int a = 0; a < 2; ++a)
#pragma unroll
        for (int b = 0; b < 8; ++b)
#pragma unroll
            for (int c = 0; c < 4; ++c) acc[a][b][c] = 0.f;

    const size_t HW = (size_t)Hin * Win;
    const float* inb = in + (size_t)n * Cin * HW;

    const int p = tid & 127;
    const int kg = tid >> 7;
    const int px = px0 + p;
    const int oh = px >> WlogO, ow = px & (WoutO - 1);

    const int arow = wco * 32 + (lane >> 2);
    const int acol = lane & 3;
    const int brow = (lane >> 2);

    for (int tap = 0; tap < 16; ++tap) {
        const int kh = tap >> 2, kw = tap & 3;
        const int ih = 2 * oh + kh - 1, iw = 2 * ow + kw - 1;
        const bool ok = (unsigned)ih < (unsigned)Hin && (unsigned)iw < (unsigned)Win;
        const float* cb = inb + (size_t)ih * Win + iw;
        for (int ch = 0; ch < nCh; ++ch) {
            __syncthreads();
            // stage A: copy pre-split tf32 tiles (4096 u32 each)
            {
                size_t tb = ((size_t)(tap * nCh + ch) * nCoB + cob) * 4096;
                const uint4* s0 = (const uint4*)(g_wT0 + tb);
                const uint4* s1 = (const uint4*)(g_wT1 + tb);
                uint4* d0 = (uint4*)(smem);
                uint4* d1 = (uint4*)(smem + 16384);
                for (int i = tid; i < 1024; i += 256) { d0[i] = s0[i]; d1[i] = s1[i]; }
            }
            // stage B: im2col [128px][32 kk] tf32 split
            {
                const float* cc = cb + (size_t)(ch * 32) * HW;
                char* b0c = smem + 32768;
                char* b1c = smem + 49152;
#pragma unroll
                for (int i = 0; i < 16; ++i) {
                    int kk = kg + i * 2;
                    float v = ok ? cc[(size_t)kk * HW] : 0.f;
                    uint32_t hi = to_tf32(v);
                    uint32_t lo = to_tf32(v - __uint_as_float(hi));
                    uint32_t off = SWZ128((uint32_t)(p * 128 + kk * 4));
                    *(uint32_t*)(b0c + off) = hi;
                    *(uint32_t*)(b1c + off) = lo;
                }
            }
            __syncthreads();
#pragma unroll
            for (int ks = 0; ks < 4; ++ks) {
                const int k0 = ks * 8;
                uint32_t a0f[2][4], a1f[2][4];
#pragma unroll
                for (int mt = 0; mt < 2; ++mt) {
#pragma unroll
                    for (int i = 0; i < 4; ++i) {
                        uint32_t off = SWZ128((uint32_t)((arow + mt * 16 + (i & 1) * 8) * 128 + (k0 + acol + (i >> 1) * 4) * 4));
                        a0f[mt][i] = *(const uint32_t*)(smem + off);
                        a1f[mt][i] = *(const uint32_t*)(smem + 16384 + off);
                    }
                }
#pragma unroll
                for (int nt = 0; nt < 8; ++nt) {
                    uint32_t b0f[2], b1f[2];
#pragma unroll
                    for (int j = 0; j < 2; ++j) {
                        uint32_t off = SWZ128((uint32_t)((wpx * 64 + nt * 8 + brow) * 128 + (k0 + acol + j * 4) * 4));
                        b0f[j] = *(const uint32_t*)(smem + 32768 + off);
                        b1f[j] = *(const uint32_t*)(smem + 49152 + off);
                    }
#pragma unroll
                    for (int mt = 0; mt < 2; ++mt) {
                        mma1688_tf(acc[mt][nt], a0f[mt], b0f[0], b0f[1]);
                        mma1688_tf(acc[mt][nt], a1f[mt], b0f[0], b0f[1]);
                        mma1688_tf(acc[mt][nt], a0f[mt], b1f[0], b1f[1]);
                    }
                }
            }
        }
    }
    // epilogue
    const int qr = lane >> 2, qc = (lane & 3) * 2;
    const size_t HWo = HW >> 2;
#pragma unroll
    for (int mt = 0; mt < 2; ++mt) {
#pragma unroll
        for (int half = 0; half < 2; ++half) {
            int co = cob * 128 + wco * 32 + mt * 16 + qr + half * 8;
            float b = bias[co];
            float* ob = out + ((size_t)n * Cout + co) * HWo;
#pragma unroll
            for (int nt = 0; nt < 8; ++nt) {
                int pxl = px0 + wpx * 64 + nt * 8 + qc;
                ob[pxl]     = acc[mt][nt][half * 2 + 0] + b;
                ob[pxl + 1] = acc[mt][nt][half * 2 + 1] + b;
            }
        }
    }
}

// ======= bf16 HMMA transposed conv k4 s2 p1: per parity class, D[128co x 128px] =======
// smem: A0 @0, A1 @16384, B0 @32768, B1 @49152. 64K dynamic.
__global__ __launch_bounds__(256) void convt_mma(
    const float* __restrict__ in, const float* __restrict__ bias, float* __restrict__ out,
    int Cin, int Cout, int Hin, int Wlog, int nCh, int nCoB)
{
    extern __shared__ __align__(128) char smem[];
    const uint32_t sb = smem_u32(smem);
    const int tid = threadIdx.x;
    const int lane = tid & 31, wid = tid >> 5;
    const int wco = wid & 3, wpx = wid >> 2;
    const int Win = 1 << Wlog;
    const int Wout = Win << 1;
    const int n = blockIdx.z >> 2;
    const int cls = blockIdx.z & 3;
    const int ph = cls >> 1, pw = cls & 1;
    const int px0 = blockIdx.x * 128;
    const int cob = blockIdx.y;

    float acc[2][8][4];
#pragma unroll
    for (int a = 0; a < 2; ++a)
#pragma unroll
        for (int b = 0; b < 8; ++b)
#pragma unroll
            for (int c = 0; c < 4; ++c) acc[a][b][c] = 0.f;

    const size_t HW = (size_t)Hin << Wlog;
    const float* inb = in + (size_t)n * Cin * HW;

    const int p = tid & 127;
    const int kg = tid >> 7;
    const int pxs = px0 + p;
    const int th = pxs >> Wlog, tw = pxs & (Win - 1);

    const int rA0 = (wco * 32 + (lane & 15)) * 128;
    const int rA1 = rA0 + 2048;
    const int aC  = (lane >> 4) * 16;
    const int rBl = (lane & 7) + ((lane >> 4) << 3);
    const int bC  = ((lane >> 3) & 1) * 16;

    for (int d = 0; d < 4; ++d) {
        const int dh = d >> 1, dw = d & 1;
        const int ih = th + ph + dh - 1, iw = tw + pw + dw - 1;
        const bool ok = (unsigned)ih < (unsigned)Hin && (unsigned)iw < (unsigned)Win;
        const float* cb = inb + (size_t)ih * Win + iw;
        const int khw = (ph + 2 * dh) * 4 + (pw + 2 * dw);
        for (int ch = 0; ch < nCh; ++ch) {
            __syncthreads();
            {
                size_t tb = ((size_t)(khw * nCh + ch) * nCoB + cob) * 8192;
                const uint4* s0 = (const uint4*)(g_wA0 + tb);
                const uint4* s1 = (const uint4*)(g_wA1 + tb);
                uint4* d0 = (uint4*)(smem);
                uint4* d1 = (uint4*)(smem + 16384);
                for (int i = tid; i < 1024; i += 256) { d0[i] = s0[i]; d1[i] = s1[i]; }
            }
            {
                char* b0c = smem + 32768;
                char* b1c = smem + 49152;
                const float* cc = cb + (size_t)(ch * 64) * HW;
#pragma unroll
                for (int i = 0; i < 32; ++i) {
                    int kk = kg + i * 2;
                    float v = ok ? cc[(size_t)kk * HW] : 0.f;
                    __nv_bfloat16 h0 = __float2bfloat16(v);
                    __nv_bfloat16 h1 = __float2bfloat16(v - __bfloat162float(h0));
                    uint32_t off = SWZ128((uint32_t)(p * 128 + kk * 2));
                    *(__nv_bfloat16*)(b0c + off) = h0;
                    *(__nv_bfloat16*)(b1c + off) = h1;
                }
            }
            __syncthreads();
#pragma unroll 1
            for (int pass = 0; pass < 3; ++pass) {
                const uint32_t Ab = sb + ((pass == 2) ? 16384u : 0u);
                const uint32_t Bb = sb + ((pass == 1) ? 49152u : 32768u);
#pragma unroll
                for (int ks = 0; ks < 4; ++ks) {
                    const int kb = ks * 32;
                    uint32_t af0[4], af1[4];
                    ldsm4(af0, Ab + SWZ128((uint32_t)(rA0 + kb + aC)));
                    ldsm4(af1, Ab + SWZ128((uint32_t)(rA1 + kb + aC)));
#pragma unroll
                    for (int j = 0; j < 4; ++j) {
                        uint32_t bf[4];
                        int rB = (wpx * 64 + j * 16 + rBl) * 128;
                        ldsm4(bf, Bb + SWZ128((uint32_t)(rB + kb + bC)));
                        mma16816(acc[0][2 * j],     af0, bf[0], bf[1]);
                        mma16816(acc[0][2 * j + 1], af0, bf[2], bf[3]);
                        mma16816(acc[1][2 * j],     af1, bf[0], bf[1]);
                        mma16816(acc[1][2 * j + 1], af1, bf[2], bf[3]);
                    }
                }
            }
        }
    }
    const int qr = lane >> 2, qc = (lane & 3) * 2;
    const size_t HWo = (size_t)(Hin << 1) * Wout;
#pragma unroll
    for (int mt = 0; mt < 2; ++mt) {
#pragma unroll
        for (int half = 0; half < 2; ++half) {
            int co = cob * 128 + wco * 32 + mt * 16 + qr + half * 8;
            float b = bias[co];
            float* ob = out + ((size_t)n * Cout + co) * HWo;
#pragma unroll
            for (int nt = 0; nt < 8; ++nt) {
                int pxl = px0 + wpx * 64 + nt * 8 + qc;
                int th2 = pxl >> Wlog, tw2 = pxl & (Win - 1);
                size_t o = (size_t)(2 * th2 + ph) * Wout + 2 * tw2 + pw;
                ob[o]     = acc[mt][nt][half * 2 + 0] + b;
                ob[o + 2] = acc[mt][nt][half * 2 + 1] + b;
            }
        }
    }
}

// packed f32x2 FMA
__device__ __forceinline__ void ffma2(float2& acc, float2 a, float2 b) {
    unsigned long long ua = *reinterpret_cast<unsigned long long*>(&a);
    unsigned long long ub = *reinterpret_cast<unsigned long long*>(&b);
    unsigned long long uc = *reinterpret_cast<unsigned long long*>(&acc);
    asm("fma.rn.f32x2 %0, %1, %2, %0;" : "+l"(uc) : "l"(ua), "l"(ub));
    acc = *reinterpret_cast<float2*>(&uc);
}

// =============== SIMT stride-2 conv (enc0 only) ===============
__global__ __launch_bounds__(256, 2) void conv_s2_big(
    const float* __restrict__ in, const float* __restrict__ w,
    const float* __restrict__ bias, float* __restrict__ out,
    int Cin, int Cout, int Hin, int Win)
{
    const int Hout = Hin >> 1, Wout = Win >> 1;
    const int tilesX = Wout >> 4;
    const int oh0 = (blockIdx.x / tilesX) << 3;
    const int ow0 = (blockIdx.x % tilesX) << 4;
    const int cob = blockIdx.y << 7;
    const int n = blockIdx.z;

    __shared__ __align__(8)  float P[4][18][36];
    __shared__ __align__(16) float Wt[4][16][132];

    const int tid = threadIdx.x;
    const int colx = tid & 15;
    const int cog  = tid >> 4;

    float2 acc[8][4];
#pragma unroll
    for (int r = 0; r < 8; ++r)
#pragma unroll
        for (int k = 0; k < 4; ++k) acc[r][k] = make_float2(0.f, 0.f);

    const float* inb = in + (size_t)n * Cin * Hin * Win;

    for (int c0 = 0; c0 < Cin; c0 += 4) {
        for (int idx = tid; idx < 8192; idx += 256) {
            int khw = idx & 15, r = idx >> 4;
            int co = r & 127, c = r >> 7;
            float v = 0.f;
            if (c0 + c < Cin)
                v = w[((size_t)(cob + co) * Cin + c0 + c) * 16 + khw];
            Wt[c][khw][co] = v;
        }
        for (int idx = tid; idx < 2448; idx += 256) {
            int c = idx / 612, r = idx - c * 612;
            int pr = r / 34, pc = r - pr * 34;
            int ih = 2 * oh0 - 1 + pr, iw = 2 * ow0 - 1 + pc;
            float v = 0.f;
            if (c0 + c < Cin && (unsigned)ih < (unsigned)Hin && (unsigned)iw < (unsigned)Win)
                v = inb[((size_t)(c0 + c) * Hin + ih) * Win + iw];
            P[c][pr][pc] = v;
        }
        __syncthreads();

#pragma unroll 1
        for (int c = 0; c < 4; ++c) {
#pragma unroll
            for (int kh = 0; kh < 4; ++kh) {
#pragma unroll
                for (int kwp = 0; kwp < 2; ++kwp) {
                    float2 av[8];
#pragma unroll
                    for (int r = 0; r < 8; ++r)
                        av[r] = *reinterpret_cast<const float2*>(&P[c][2 * r + kh][2 * colx + 2 * kwp]);
                    const int khw0 = (kh << 2) + 2 * kwp;
                    const float4* w0 = reinterpret_cast<const float4*>(&Wt[c][khw0][cog << 3]);
                    const float4* w1 = reinterpret_cast<const float4*>(&Wt[c][khw0 + 1][cog << 3]);
                    float4 wA0 = w0[0], wB0 = w0[1];
                    float4 wA1 = w1[0], wB1 = w1[1];
                    float2 p00 = make_float2(wA0.x, wA0.y), p01 = make_float2(wA0.z, wA0.w);
                    float2 p02 = make_float2(wB0.x, wB0.y), p03 = make_float2(wB0.z, wB0.w);
                    float2 p10 = make_float2(wA1.x, wA1.y), p11 = make_float2(wA1.z, wA1.w);
                    float2 p12 = make_float2(wB1.x, wB1.y), p13 = make_float2(wB1.z, wB1.w);
#pragma unroll
                    for (int r = 0; r < 8; ++r) {
                        float2 ax = make_float2(av[r].x, av[r].x);
                        float2 ay = make_float2(av[r].y, av[r].y);
                        ffma2(acc[r][0], ax, p00);
                        ffma2(acc[r][1], ax, p01);
                        ffma2(acc[r][2], ax, p02);
                        ffma2(acc[r][3], ax, p03);
                        ffma2(acc[r][0], ay, p10);
                        ffma2(acc[r][1], ay, p11);
                        ffma2(acc[r][2], ay, p12);
                        ffma2(acc[r][3], ay, p13);
                    }
                }
            }
        }
        __syncthreads();
    }

#pragma unroll
    for (int kp = 0; kp < 4; ++kp) {
        int co = cob + (cog << 3) + (kp << 1);
        float b0 = bias[co], b1 = bias[co + 1];
        float* o0 = out + (((size_t)n * Cout + co) * Hout + oh0) * Wout + ow0 + colx;
        float* o1 = o0 + (size_t)Hout * Wout;
#pragma unroll
        for (int r = 0; r < 8; ++r) {
            o0[(size_t)r * Wout] = acc[r][kp].x + b0;
            o1[(size_t)r * Wout] = acc[r][kp].y + b1;
        }
    }
}

// =============== final transposed conv 128->3 + tanh ===============
__global__ __launch_bounds__(256) void convt_final_kernel(
    const float* __restrict__ in, const float* __restrict__ w,
    const float* __restrict__ bias, float* __restrict__ out)
{
    const int n = blockIdx.y;
    const int oh0 = (blockIdx.x >> 4) << 4;
    const int ow0 = (blockIdx.x & 15) << 4;
    __shared__ float P[8][10][11];
    __shared__ float Wsm[8][3][17];
    const int tid = threadIdx.x;
    const int py = tid >> 4, px = tid & 15;
    const int ph = py & 1, pw = px & 1;
    const int ihl0 = (py + ph) >> 1, iwl0 = (px + pw) >> 1;
    const int r0 = (oh0 >> 1) - 1, col0 = (ow0 >> 1) - 1;
    float acc0 = 0.f, acc1 = 0.f, acc2 = 0.f;
    const float* inb = in + ((size_t)n << 21);

    for (int c0 = 0; c0 < 128; c0 += 8) {
        for (int idx = tid; idx < 800; idx += 256) {
            int c = idx / 100, r = idx - c * 100;
            int rr = r / 10, cc = r - rr * 10;
            int ih = r0 + rr, iw = col0 + cc;
            float v = 0.f;
            if ((unsigned)ih < 128u && (unsigned)iw < 128u)
                v = inb[((size_t)(c0 + c) << 14) + (ih << 7) + iw];
            P[c][rr][cc] = v;
        }
        for (int idx = tid; idx < 384; idx += 256) {
            int c = idx / 48, r = idx - c * 48;
            int co = r >> 4, khw = r & 15;
            Wsm[c][co][khw] = w[((size_t)co * 128 + c0 + c) * 16 + khw];
        }
        __syncthreads();
#pragma unroll
        for (int c = 0; c < 8; ++c) {
#pragma unroll
            for (int dh = 0; dh < 2; ++dh) {
#pragma unroll
                for (int dw = 0; dw < 2; ++dw) {
                    float a = P[c][ihl0 + dh][iwl0 + dw];
                    int khw = ((ph + (dh << 1)) << 2) + pw + (dw << 1);
                    acc0 += a * Wsm[c][0][khw];
                    acc1 += a * Wsm[c][1][khw];
                    acc2 += a * Wsm[c][2][khw];
                }
            }
        }
        __syncthreads();
    }
    const int oh = oh0 + py, ow = ow0 + px;
    size_t base = ((size_t)n * 3) * 65536 + ((size_t)oh << 8) + ow;
    out[base]          = tanhf(acc0 + bias[0]);
    out[base + 65536]  = tanhf(acc1 + bias[1]);
    out[base + 131072] = tanhf(acc2 + bias[2]);
}

// =============== group-norm stats ===============
__global__ __launch_bounds__(256) void gn_stats_kernel(const float* __restrict__ x, int span)
{
    const float* p = x + (size_t)blockIdx.x * span;
    float s = 0.f, ss = 0.f;
    for (int i = threadIdx.x; i < span; i += 256) {
        float v = p[i];
        s += v; ss += v * v;
    }
#pragma unroll
    for (int o = 16; o; o >>= 1) {
        s  += __shfl_down_sync(0xffffffffu, s, o);
        ss += __shfl_down_sync(0xffffffffu, ss, o);
    }
    __shared__ float as[8], bs[8];
    int wi = threadIdx.x >> 5, l = threadIdx.x & 31;
    if (l == 0) { as[wi] = s; bs[wi] = ss; }
    __syncthreads();
    if (threadIdx.x == 0) {
        s = 0.f; ss = 0.f;
#pragma unroll
        for (int i = 0; i < 8; ++i) { s += as[i]; ss += bs[i]; }
        float m = s / (float)span;
        float var = ss / (float)span - m * m;
        g_mean[blockIdx.x] = m;
        g_rstd[blockIdx.x] = rsqrtf(var + 1e-5f);
    }
}

// =============== fused GN apply + SiLU ===============
__global__ __launch_bounds__(256) void gn_apply_silu_kernel(
    float* __restrict__ x, const float* __restrict__ gamma, const float* __restrict__ beta,
    int C, int HW, int cpg)
{
    size_t i = (size_t)blockIdx.x * 256 + threadIdx.x;
    size_t e = i * 4;
    size_t ch = e / (size_t)HW;
    int c = (int)(ch % C);
    int n = (int)(ch / C);
    int gi = n * 32 + c / cpg;
    float m = g_mean[gi], r = g_rstd[gi];
    float ga = gamma[c], be = beta[c];
    float4 v = *reinterpret_cast<float4*>(x + e);
    float y;
    y = (v.x - m) * r * ga + be; v.x = y / (1.f + expf(-y));
    y = (v.y - m) * r * ga + be; v.y = y / (1.f + expf(-y));
    y = (v.z - m) * r * ga + be; v.z = y / (1.f + expf(-y));
    y = (v.w - m) * r * ga + be; v.w = y / (1.f + expf(-y));
    *reinterpret_cast<float4*>(x + e) = v;
}

// =============== 1x1 conv 512->32 ===============
__global__ __launch_bounds__(256) void conv1x1_enc3_kernel(
    const float* __restrict__ in, const float* __restrict__ w,
    const float* __restrict__ bias, float* __restrict__ out)
{
    const int t = blockIdx.x * 256 + threadIdx.x;
    const int n = t >> 10, pix = t & 1023;
    __shared__ float wsm[128][33];
    float acc[32];
#pragma unroll
    for (int k = 0; k < 32; ++k) acc[k] = 0.f;
    for (int c0 = 0; c0 < 512; c0 += 128) {
        __syncthreads();
        for (int idx = threadIdx.x; idx < 4096; idx += 256) {
            int co = idx >> 7, cc = idx & 127;
            wsm[cc][co] = w[(size_t)co * 512 + c0 + cc];
        }
        __syncthreads();
        for (int cc = 0; cc < 128; ++cc) {
            float a = in[(((size_t)n * 512 + c0 + cc) << 10) + pix];
#pragma unroll
            for (int k = 0; k < 32; ++k) acc[k] += a * wsm[cc][k];
        }
    }
#pragma unroll
    for (int k = 0; k < 32; ++k)
        out[(((size_t)n * 32 + k) << 10) + pix] = acc[k] + bias[k];
}

// =============== vector quantization ===============
__global__ __launch_bounds__(256) void vq_kernel(
    const float* __restrict__ z, const float* __restrict__ cbk,
    float* __restrict__ q, float* __restrict__ outq, float* __restrict__ outidx)
{
    const int m = blockIdx.x * 256 + threadIdx.x;
    float v[32];
#pragma unroll
    for (int j = 0; j < 32; ++j) v[j] = z[(size_t)m * 32 + j];
    __shared__ float csm[128][33];
    __shared__ float c2sm[128];
    float best = 3.4e38f;
    int bi = 0;
    for (int k0 = 0; k0 < 1024; k0 += 128) {
        __syncthreads();
        for (int idx = threadIdx.x; idx < 4096; idx += 256)
            csm[idx >> 5][idx & 31] = cbk[(size_t)k0 * 32 + idx];
        __syncthreads();
        if (threadIdx.x < 128) {
            float s = 0.f;
#pragma unroll
            for (int j = 0; j < 32; ++j) { float c = csm[threadIdx.x][j]; s += c * c; }
            c2sm[threadIdx.x] = s;
        }
        __syncthreads();
        for (int k = 0; k < 128; ++k) {
            float dot = 0.f;
#pragma unroll
            for (int j = 0; j < 32; ++j) dot += v[j] * csm[k][j];
            float d = c2sm[k] - 2.f * dot;
            if (d < best) { best = d; bi = k0 + k; }
        }
    }
#pragma unroll
    for (int j = 0; j < 32; ++j) {
        float qv = cbk[(size_t)bi * 32 + j];
        q[(size_t)m * 32 + j] = qv;
        outq[(size_t)m * 32 + j] = qv;
    }
    outidx[m] = (float)bi;
}

// =============== 1x1 conv 32->512 ===============
__global__ __launch_bounds__(256) void conv1x1_dec0_kernel(
    const float* __restrict__ q, const float* __restrict__ w,
    const float* __restrict__ bias, float* __restrict__ out)
{
    const int n = blockIdx.x >> 4;
    const int pix0 = (blockIdx.x & 15) << 6;
    const int cob = blockIdx.y << 6;
    __shared__ float qsm[32][64];
    __shared__ float wsm[32][65];
    const int tid = threadIdx.x;
    const int p = tid & 63, cg = tid >> 6;
    for (int idx = tid; idx < 2048; idx += 256) {
        int ci = idx >> 6, pp = idx & 63;
        qsm[ci][pp] = q[(((size_t)n * 32 + ci) << 10) + pix0 + pp];
    }
    for (int idx = tid; idx < 2048; idx += 256) {
        int co = idx >> 5, ci = idx & 31;
        wsm[ci][co] = w[((size_t)(cob + co) << 5) + ci];
    }
    __syncthreads();
    float acc[16];
#pragma unroll
    for (int k = 0; k < 16; ++k) acc[k] = 0.f;
#pragma unroll
    for (int ci = 0; ci < 32; ++ci) {
        float a = qsm[ci][p];
#pragma unroll
        for (int k = 0; k < 16; ++k)
            acc[k] += a * wsm[ci][(cg << 4) + k];
    }
#pragma unroll
    for (int k = 0; k < 16; ++k) {
        int co = cob + (cg << 4) + k;
        out[(((size_t)n * 512 + co) << 10) + pix0 + p] = acc[k] + bias[co];
    }
}

// =================================================================================
extern "C" void kernel_launch(void* const* d_in, const int* in_sizes, int n_in,
                              void* d_out, int out_size)
{
    const float* x       = (const float*)d_in[0];
    const float* enc0_w  = (const float*)d_in[1];
    const float* enc0_b  = (const float*)d_in[2];
    const float* enc0_g  = (const float*)d_in[3];
    const float* enc0_bt = (const float*)d_in[4];
    const float* enc1_w  = (const float*)d_in[5];
    const float* enc1_b  = (const float*)d_in[6];
    const float* enc1_g  = (const float*)d_in[7];
    const float* enc1_bt = (const float*)d_in[8];
    const float* enc2_w  = (const float*)d_in[9];
    const float* enc2_b  = (const float*)d_in[10];
    const float* enc2_g  = (const float*)d_in[11];
    const float* enc2_bt = (const float*)d_in[12];
    const float* enc3_w  = (const float*)d_in[13];
    const float* enc3_b  = (const float*)d_in[14];
    const float* codebook= (const float*)d_in[15];
    const float* dec0_w  = (const float*)d_in[16];
    const float* dec0_b  = (const float*)d_in[17];
    const float* dec1_w  = (const float*)d_in[18];
    const float* dec1_b  = (const float*)d_in[19];
    const float* dec1_g  = (const float*)d_in[20];
    const float* dec1_bt = (const float*)d_in[21];
    const float* dec2_w  = (const float*)d_in[22];
    const float* dec2_b  = (const float*)d_in[23];
    const float* dec2_g  = (const float*)d_in[24];
    const float* dec2_bt = (const float*)d_in[25];
    const float* dec3_w  = (const float*)d_in[26];
    const float* dec3_b  = (const float*)d_in[27];

    float* out = (float*)d_out;

    float *bufA, *bufB, *bufC, *bufZ, *bufQ;
    cudaGetSymbolAddress((void**)&bufA, g_bufA);
    cudaGetSymbolAddress((void**)&bufB, g_bufB);
    cudaGetSymbolAddress((void**)&bufC, g_bufC);
    cudaGetSymbolAddress((void**)&bufZ, g_bufZ);
    cudaGetSymbolAddress((void**)&bufQ, g_bufQ);

    const int TCS = 65536;
    cudaFuncSetAttribute(conv_s2_tf, cudaFuncAttributeMaxDynamicSharedMemorySize, TCS);
    cudaFuncSetAttribute(convt_mma, cudaFuncAttributeMaxDynamicSharedMemorySize, TCS);

    // ---- encoder ----
    conv_s2_big<<<dim3(128, 1, 16), 256>>>(x, enc0_w, enc0_b, bufA, 3, 128, 256, 256);
    gn_stats_kernel<<<512, 256>>>(bufA, 4 * 128 * 128);
    gn_apply_silu_kernel<<<32768, 256>>>(bufA, enc0_g, enc0_bt, 128, 128 * 128, 4);

    // enc1: tf32 HMMA (Cin=128 nCh=4, Cout=256 nCoB=2, out 64x64 -> WlogO=6)
    wsplit_tf<<<2048, 256>>>(enc1_w, 128, 4, 2);
    conv_s2_tf<<<dim3(32, 2, 16), 256, TCS>>>(bufA, enc1_b, bufB, 128, 256, 128, 128, 6, 4, 2);
    gn_stats_kernel<<<512, 256>>>(bufB, 8 * 64 * 64);
    gn_apply_silu_kernel<<<16384, 256>>>(bufB, enc1_g, enc1_bt, 256, 64 * 64, 8);

    // enc2: tf32 HMMA (Cin=256 nCh=8, Cout=512 nCoB=4, out 32x32 -> WlogO=5)
    wsplit_tf<<<8192, 256>>>(enc2_w, 256, 8, 4);
    conv_s2_tf<<<dim3(8, 4, 16), 256, TCS>>>(bufB, enc2_b, bufC, 256, 512, 64, 64, 5, 8, 4);
    gn_stats_kernel<<<512, 256>>>(bufC, 16 * 32 * 32);
    gn_apply_silu_kernel<<<8192, 256>>>(bufC, enc2_g, enc2_bt, 512, 32 * 32, 16);

    conv1x1_enc3_kernel<<<64, 256>>>(bufC, enc3_w, enc3_b, bufZ);

    // ---- VQ ----
    vq_kernel<<<64, 256>>>(bufZ, codebook, bufQ, out + 3145728, out + 3670016);

    // ---- decoder ----
    conv1x1_dec0_kernel<<<dim3(256, 8), 256>>>(bufQ, dec0_w, dec0_b, bufC);

    wsplit_kernel<<<8192, 256>>>(dec1_w, 512, 8, 2);
    convt_mma<<<dim3(8, 2, 64), 256, TCS>>>(bufC, dec1_b, bufB, 512, 256, 32, 5, 8, 2);
    gn_stats_kernel<<<512, 256>>>(bufB, 8 * 64 * 64);
    gn_apply_silu_kernel<<<16384, 256>>>(bufB, dec1_g, dec1_bt, 256, 64 * 64, 8);

    wsplit_kernel<<<2048, 256>>>(dec2_w, 256, 4, 1);
    convt_mma<<<dim3(32, 1, 64), 256, TCS>>>(bufB, dec2_b, bufA, 256, 128, 64, 6, 4, 1);
    gn_stats_kernel<<<512, 256>>>(bufA, 4 * 128 * 128);
    gn_apply_silu_kernel<<<32768, 256>>>(bufA, dec2_g, dec2_bt, 128, 128 * 128, 4);

    convt_final_kernel<<<dim3(256, 16), 256>>>(bufA, dec3_w, dec3_b, out);
}